// round 14
// baseline (speedup 1.0000x reference)
#include <cuda_runtime.h>
#include <mma.h>
#include <cuda_fp16.h>
#include <math.h>
#include <cstdint>

using namespace nvcuda;

// ---------------- problem constants ----------------
#define T_TOK 2048
#define S_LEN 1024
#define H_DIM 1024
#define NHEAD 16
#define HD    64
#define NEXP  8
#define INTER 2816
#define GU2   (2*INTER)

// ---------------- device scratch ----------------
__device__ float  g_qkv [(size_t)T_TOK * 3 * H_DIM];
__device__ __half g_qkvh[(size_t)T_TOK * 3 * H_DIM];
__device__ __half g_ctxh[(size_t)T_TOK * H_DIM];
__device__ float  g_tmp [(size_t)T_TOK * H_DIM];
__device__ float  g_hs  [(size_t)T_TOK * H_DIM];
__device__ __half g_hsh [(size_t)T_TOK * H_DIM];
__device__ __half g_acth[(size_t)T_TOK * 2 * INTER];
__device__ float  g_ypair[(size_t)T_TOK * 2 * H_DIM];
__device__ __half g_hidh[(size_t)T_TOK * H_DIM];
__device__ __half g_wqkvh[(size_t)H_DIM * 3 * H_DIM];
__device__ __half g_woh [(size_t)H_DIM * H_DIM];
__device__ __half g_wguh[(size_t)NEXP * H_DIM * GU2];
__device__ __half g_wdh [(size_t)NEXP * INTER * H_DIM];
__device__ float  g_pairw[T_TOK * 2];
__device__ int    g_cnt [NEXP];
__device__ int    g_rows[NEXP * T_TOK];

// ---------------- cp.async helpers ----------------
__device__ __forceinline__ void cp16(void* s, const void* g, bool pred) {
    unsigned int sa = (unsigned int)__cvta_generic_to_shared(s);
    int sz = pred ? 16 : 0;
    asm volatile("cp.async.cg.shared.global [%0], [%1], 16, %2;\n" :: "r"(sa), "l"(g), "r"(sz));
}
__device__ __forceinline__ void cp_commit() { asm volatile("cp.async.commit_group;\n"); }
__device__ __forceinline__ void cp_wait1()  { asm volatile("cp.async.wait_group 1;\n" ::: "memory"); }
__device__ __forceinline__ void cp_wait0()  { asm volatile("cp.async.wait_group 0;\n" ::: "memory"); }

// half-precision shared layouts (elements)
#define AH_LD 24
#define BH_LD 136
#define VH_LD 72
// f32 epilogue stages
#define CS_LD 132
#define GC_LD 68
// fused attention layouts
#define FA_QLD 72    // Q/K/V/P tiles: x72 halves
#define FA_SLD 68    // S/O tiles: x68 floats

typedef wmma::fragment<wmma::matrix_a, 16, 16, 16, __half, wmma::row_major> HFragA;
typedef wmma::fragment<wmma::matrix_b, 16, 16, 16, __half, wmma::row_major> HFragB;
typedef wmma::fragment<wmma::matrix_b, 16, 16, 16, __half, wmma::col_major> HFragBc;
typedef wmma::fragment<wmma::accumulator, 16, 16, 16, float> HFragC;

// ---------------- f32 -> f16 conversion ----------------
__global__ void cvt_kernel(const float* __restrict__ in, __half* __restrict__ out, size_t n)
{
    size_t i = ((size_t)blockIdx.x * blockDim.x + threadIdx.x) * 4;
    if (i >= n) return;
    float4 v = *(const float4*)(in + i);
    *(__half2*)(out + i)     = __floats2half2_rn(v.x, v.y);
    *(__half2*)(out + i + 2) = __floats2half2_rn(v.z, v.w);
}

// ================= plain FP16 GEMM: C_f32[M,N] = A_h[M,K] @ B_h[K,N], BK=16 =================
__global__ __launch_bounds__(256, 2) void gemm_f16_kernel(
    const __half* __restrict__ A, const __half* __restrict__ B,
    float* __restrict__ C, int M, int N, int K)
{
    __shared__ __half As[2][128 * AH_LD];
    __shared__ __half Bs[2][16 * BH_LD];

    int tx = threadIdx.x;
    int rowBase = blockIdx.y * 128;
    int colBase = blockIdx.x * 128;
    int warp = tx >> 5, wm = warp >> 1, wn = warp & 1;

    HFragC c[2][4];
#pragma unroll
    for (int mi = 0; mi < 2; mi++)
#pragma unroll
        for (int ni = 0; ni < 4; ni++) wmma::fill_fragment(c[mi][ni], 0.f);

    int arow = tx >> 1, acol = (tx & 1) * 8;
    int brow = tx >> 4, bcol = (tx & 15) * 8;
    const __half* aP = A + (size_t)(rowBase + arow) * K + acol;
    const __half* bP = B + (size_t)brow * N + colBase + bcol;
    int nt = K >> 4;

    cp16(&As[0][arow * AH_LD + acol], aP, true);
    cp16(&Bs[0][brow * BH_LD + bcol], bP, true);
    cp_commit();

    for (int t = 0; t < nt; t++) {
        int cur = t & 1, nxt = cur ^ 1;
        if (t + 1 < nt) {
            cp16(&As[nxt][arow * AH_LD + acol], aP + (t + 1) * 16, true);
            cp16(&Bs[nxt][brow * BH_LD + bcol], bP + (size_t)(t + 1) * 16 * N, true);
            cp_commit();
            cp_wait1();
        } else cp_wait0();
        __syncthreads();
        HFragA a[2]; HFragB b[4];
#pragma unroll
        for (int mi = 0; mi < 2; mi++)
            wmma::load_matrix_sync(a[mi], &As[cur][(wm * 32 + mi * 16) * AH_LD], AH_LD);
#pragma unroll
        for (int ni = 0; ni < 4; ni++)
            wmma::load_matrix_sync(b[ni], &Bs[cur][wn * 64 + ni * 16], BH_LD);
#pragma unroll
        for (int mi = 0; mi < 2; mi++)
#pragma unroll
            for (int ni = 0; ni < 4; ni++)
                wmma::mma_sync(c[mi][ni], a[mi], b[ni], c[mi][ni]);
        __syncthreads();
    }
#pragma unroll
    for (int mi = 0; mi < 2; mi++)
#pragma unroll
        for (int ni = 0; ni < 4; ni++)
            wmma::store_matrix_sync(
                &C[(size_t)(rowBase + wm * 32 + mi * 16) * N + colBase + wn * 64 + ni * 16],
                c[mi][ni], N, wmma::mem_row_major);
}

// ================= RoPE: f32 g_qkv -> f16 g_qkvh =================
__global__ void rope_kernel(const float* __restrict__ cosp, const float* __restrict__ sinp)
{
    int idx = blockIdx.x * blockDim.x + threadIdx.x;
    if (idx >= T_TOK * NHEAD * 32) return;
    int d = idx & 31;
    int n = (idx >> 5) & 15;
    int t = idx >> 9;
    int s = t & (S_LEN - 1);
    float c1 = cosp[s * 64 + d],      s1 = sinp[s * 64 + d];
    float c2 = cosp[s * 64 + d + 32], s2 = sinp[s * 64 + d + 32];
    size_t base = (size_t)t * 3072 + n * 64 + d;
    float x1 = g_qkv[base], x2 = g_qkv[base + 32];
    g_qkvh[base]      = __float2half_rn(x1 * c1 - x2 * s1);
    g_qkvh[base + 32] = __float2half_rn(x2 * c2 + x1 * s2);
    x1 = g_qkv[base + 1024]; x2 = g_qkv[base + 1056];
    g_qkvh[base + 1024] = __float2half_rn(x1 * c1 - x2 * s1);
    g_qkvh[base + 1056] = __float2half_rn(x2 * c2 + x1 * s2);
    g_qkvh[base + 2048] = __float2half_rn(g_qkv[base + 2048]);
    g_qkvh[base + 2080] = __float2half_rn(g_qkv[base + 2080]);
}

// ================= FUSED flash attention — 64-row q tiles, 2 CTAs/SM =================
// grid (16 qtiles, 32 bh), 256 threads (8 warps: 4m x 2n on 64x64 tiles).
// smem (bytes): Qs[64x72]h:0  Ks[2][64x72]h:9216  Vs:27648  Ps[64x72]h:46080
//               Ss[64x68]f:55296  Os[64x68]f:72704  mrow:90112  lrow:90368  tot 90624
__global__ __launch_bounds__(256, 2) void attn_fused_kernel()
{
    extern __shared__ char smraw[];
    __half* Qs = (__half*)smraw;
    __half* Ks = (__half*)(smraw + 9216);
    __half* Vs = (__half*)(smraw + 27648);
    __half* Ps = (__half*)(smraw + 46080);
    float*  Ss = (float*)(smraw + 55296);
    float*  Os = (float*)(smraw + 72704);
    float*  mrow = (float*)(smraw + 90112);
    float*  lrow = (float*)(smraw + 90368);

    int z = blockIdx.y;
    int b = z >> 4, h = z & 15;
    int qBase = blockIdx.x * 64;
    int tbase = b * S_LEN;
    int tx = threadIdx.x;
    int warp = tx >> 5, wm = warp >> 1, wn = warp & 1;   // wm 0..3 (16 rows), wn 0..1 (32 cols)

    // --- prologue ---
    {
        int r = tx >> 2, cs = (tx & 3) * 16;
        const __half* qp = g_qkvh + (size_t)(tbase + qBase + r) * 3072 + h * 64 + cs;
        cp16(&Qs[r * FA_QLD + cs], qp, true);
        cp16(&Qs[r * FA_QLD + cs + 8], qp + 8, true);
        const __half* kp = g_qkvh + (size_t)(tbase + r) * 3072 + 1024 + h * 64 + cs;
        cp16(&Ks[r * FA_QLD + cs], kp, true);
        cp16(&Ks[r * FA_QLD + cs + 8], kp + 8, true);
        cp16(&Vs[r * FA_QLD + cs], kp + 1024, true);
        cp16(&Vs[r * FA_QLD + cs + 8], kp + 1024 + 8, true);
        cp_commit();
    }
#pragma unroll
    for (int j = 0; j < 17; j++) Os[tx + j * 256] = 0.f;   // 64*68 = 4352
    if (tx < 64) { mrow[tx] = -1e30f; lrow[tx] = 0.f; }
    cp_wait0();
    __syncthreads();

    const int row4 = tx >> 2, q4 = tx & 3;                  // softmax mapping: 4 thr/row, 16 cols

    for (int t = 0; t < 16; t++) {
        int cur = t & 1, nxt = cur ^ 1;
        if (t + 1 < 16) {
            int r = tx >> 2, cs = (tx & 3) * 16;
            const __half* kp = g_qkvh + (size_t)(tbase + (t + 1) * 64 + r) * 3072 + 1024 + h * 64 + cs;
            cp16(&Ks[nxt * 64 * FA_QLD + r * FA_QLD + cs], kp, true);
            cp16(&Ks[nxt * 64 * FA_QLD + r * FA_QLD + cs + 8], kp + 8, true);
            cp16(&Vs[nxt * 64 * FA_QLD + r * FA_QLD + cs], kp + 1024, true);
            cp16(&Vs[nxt * 64 * FA_QLD + r * FA_QLD + cs + 8], kp + 1024 + 8, true);
            cp_commit();
        }

        // --- phase 1: S = 0.125 * Q @ K^T (64x64) ---
        {
            HFragC cs2[2];
#pragma unroll
            for (int ni = 0; ni < 2; ni++) wmma::fill_fragment(cs2[ni], 0.f);
#pragma unroll
            for (int kk = 0; kk < 4; kk++) {
                HFragA a; HFragBc bb[2];
                wmma::load_matrix_sync(a, &Qs[(wm * 16) * FA_QLD + kk * 16], FA_QLD);
#pragma unroll
                for (int ni = 0; ni < 2; ni++)
                    wmma::load_matrix_sync(bb[ni], &Ks[cur * 64 * FA_QLD + (wn * 32 + ni * 16) * FA_QLD + kk * 16], FA_QLD);
#pragma unroll
                for (int ni = 0; ni < 2; ni++)
                    wmma::mma_sync(cs2[ni], a, bb[ni], cs2[ni]);
            }
#pragma unroll
            for (int ni = 0; ni < 2; ni++) {
#pragma unroll
                for (int i = 0; i < cs2[ni].num_elements; i++) cs2[ni].x[i] *= 0.125f;
                wmma::store_matrix_sync(&Ss[(wm * 16) * FA_SLD + wn * 32 + ni * 16],
                                        cs2[ni], FA_SLD, wmma::mem_row_major);
            }
        }
        __syncthreads();

        // --- phase 2: online softmax + O rescale (4 threads/row, 16 cols each) ---
        {
            const float* srow = &Ss[row4 * FA_SLD + q4 * 16];
            float s[16];
            float tmax = -1e30f;
#pragma unroll
            for (int i = 0; i < 16; i++) { s[i] = srow[i]; tmax = fmaxf(tmax, s[i]); }
            tmax = fmaxf(tmax, __shfl_xor_sync(0xffffffffu, tmax, 1));
            tmax = fmaxf(tmax, __shfl_xor_sync(0xffffffffu, tmax, 2));
            float m_old = mrow[row4];
            float m_new = fmaxf(m_old, tmax);
            float alpha = __expf(m_old - m_new);
            float psum = 0.f;
            __half* prow = &Ps[row4 * FA_QLD + q4 * 16];
#pragma unroll
            for (int i = 0; i < 16; i += 2) {
                float p0 = __expf(s[i] - m_new);
                float p1 = __expf(s[i + 1] - m_new);
                psum += p0 + p1;
                *(__half2*)(prow + i) = __floats2half2_rn(p0, p1);
            }
            psum += __shfl_xor_sync(0xffffffffu, psum, 1);
            psum += __shfl_xor_sync(0xffffffffu, psum, 2);
            if (q4 == 0) {
                mrow[row4] = m_new;
                lrow[row4] = lrow[row4] * alpha + psum;
            }
            float* orow = &Os[row4 * FA_SLD + q4 * 16];
#pragma unroll
            for (int i = 0; i < 16; i++) orow[i] *= alpha;
        }
        __syncthreads();

        // --- phase 3: O += P @ V ---
        {
            HFragC co[2];
#pragma unroll
            for (int ni = 0; ni < 2; ni++)
                wmma::load_matrix_sync(co[ni], &Os[(wm * 16) * FA_SLD + wn * 32 + ni * 16],
                                       FA_SLD, wmma::mem_row_major);
#pragma unroll
            for (int kk = 0; kk < 4; kk++) {
                HFragA a; HFragB bb[2];
                wmma::load_matrix_sync(a, &Ps[(wm * 16) * FA_QLD + kk * 16], FA_QLD);
#pragma unroll
                for (int ni = 0; ni < 2; ni++)
                    wmma::load_matrix_sync(bb[ni], &Vs[cur * 64 * FA_QLD + (kk * 16) * FA_QLD + wn * 32 + ni * 16], FA_QLD);
#pragma unroll
                for (int ni = 0; ni < 2; ni++)
                    wmma::mma_sync(co[ni], a, bb[ni], co[ni]);
            }
#pragma unroll
            for (int ni = 0; ni < 2; ni++)
                wmma::store_matrix_sync(&Os[(wm * 16) * FA_SLD + wn * 32 + ni * 16],
                                        co[ni], FA_SLD, wmma::mem_row_major);
        }
        if (t + 1 < 16) cp_wait0();
        __syncthreads();
    }

    // --- epilogue ---
    {
        float inv = 1.f / lrow[row4];
        const float* orow = &Os[row4 * FA_SLD + q4 * 16];
        __half* dst = g_ctxh + (size_t)(tbase + qBase + row4) * H_DIM + h * 64 + q4 * 16;
#pragma unroll
        for (int i = 0; i < 16; i += 2)
            *(__half2*)(dst + i) = __floats2half2_rn(orow[i] * inv, orow[i + 1] * inv);
    }
}

// ================= MoE gate_up fused silu — grid x=mtile (L2 reuse of B) =================
__global__ __launch_bounds__(256, 2) void moe_gateup_kernel()
{
    extern __shared__ char smraw[];
    __half* As = (__half*)smraw;
    __half* Bg = As + 2 * 128 * AH_LD;
    __half* Bu = Bg + 2 * 16 * VH_LD;
    float*  Cs = (float*)smraw;
    __shared__ int sPid[128];

    int e = blockIdx.z;
    int count = g_cnt[e];
    int mBase = blockIdx.x * 128;          // x = mtile: adjacent blocks share B slab
    if (mBase >= count) return;
    int nBase = blockIdx.y * 64;

    int tx = threadIdx.x;
    if (tx < 128) {
        int r = mBase + tx;
        sPid[tx] = (r < count) ? g_rows[e * T_TOK + r] : -1;
    }
    __syncthreads();

    const __half* B = g_wguh + (size_t)e * H_DIM * GU2;
    int warp = tx >> 5, wm = warp >> 1, wn = warp & 1;

    HFragC cg[2][2], cu[2][2];
#pragma unroll
    for (int mi = 0; mi < 2; mi++)
#pragma unroll
        for (int ni = 0; ni < 2; ni++) { wmma::fill_fragment(cg[mi][ni], 0.f); wmma::fill_fragment(cu[mi][ni], 0.f); }

    int arow = tx >> 1, acol = (tx & 1) * 8;
    int pidA = sPid[arow];
    bool valid = (pidA >= 0);
    const __half* aP = g_hsh + (valid ? (size_t)(pidA >> 1) * H_DIM : 0) + acol;
    int btx = tx & 127;
    int brow = btx >> 3, bcol = (btx & 7) * 8;
    bool isUp = (tx >= 128);
    const __half* bP = B + (size_t)brow * GU2 + nBase + bcol + (isUp ? INTER : 0);
    __half* Bdst = isUp ? Bu : Bg;
    const int nt = H_DIM >> 4;

    cp16(&As[arow * AH_LD + acol], aP, valid);
    cp16(&Bdst[brow * VH_LD + bcol], bP, true);
    cp_commit();

    for (int t = 0; t < nt; t++) {
        int cur = t & 1, nxt = cur ^ 1;
        if (t + 1 < nt) {
            cp16(&As[nxt * 128 * AH_LD + arow * AH_LD + acol], aP + (t + 1) * 16, valid);
            cp16(&Bdst[nxt * 16 * VH_LD + brow * VH_LD + bcol], bP + (size_t)(t + 1) * 16 * GU2, true);
            cp_commit();
            cp_wait1();
        } else cp_wait0();
        __syncthreads();
        HFragA a[2];
#pragma unroll
        for (int mi = 0; mi < 2; mi++)
            wmma::load_matrix_sync(a[mi], &As[cur * 128 * AH_LD + (wm * 32 + mi * 16) * AH_LD], AH_LD);
#pragma unroll
        for (int ni = 0; ni < 2; ni++) {
            HFragB bg;
            wmma::load_matrix_sync(bg, &Bg[cur * 16 * VH_LD + wn * 32 + ni * 16], VH_LD);
#pragma unroll
            for (int mi = 0; mi < 2; mi++)
                wmma::mma_sync(cg[mi][ni], a[mi], bg, cg[mi][ni]);
            HFragB bu;
            wmma::load_matrix_sync(bu, &Bu[cur * 16 * VH_LD + wn * 32 + ni * 16], VH_LD);
#pragma unroll
            for (int mi = 0; mi < 2; mi++)
                wmma::mma_sync(cu[mi][ni], a[mi], bu, cu[mi][ni]);
        }
        __syncthreads();
    }

#pragma unroll
    for (int mi = 0; mi < 2; mi++)
#pragma unroll
        for (int ni = 0; ni < 2; ni++) {
#pragma unroll
            for (int i = 0; i < cg[mi][ni].num_elements; i++) {
                float g = cg[mi][ni].x[i];
                cg[mi][ni].x[i] = g / (1.f + __expf(-g)) * cu[mi][ni].x[i];
            }
            wmma::store_matrix_sync(&Cs[(wm * 32 + mi * 16) * GC_LD + wn * 32 + ni * 16],
                                    cg[mi][ni], GC_LD, wmma::mem_row_major);
        }
    __syncthreads();

    int orow = tx >> 1, ocol = (tx & 1) * 32;
    int pid = sPid[orow];
    if (pid >= 0) {
        __half* dst = g_acth + (size_t)pid * INTER + nBase + ocol;
        const float* src = &Cs[orow * GC_LD + ocol];
#pragma unroll
        for (int i = 0; i < 16; i++)
            *(__half2*)(dst + i * 2) = __floats2half2_rn(src[i * 2], src[i * 2 + 1]);
    }
}

// ================= MoE down (fp16) — grid x=mtile =================
__global__ __launch_bounds__(256, 2) void moe_down_kernel()
{
    extern __shared__ char smraw[];
    __half* As = (__half*)smraw;
    __half* Bs = As + 2 * 128 * AH_LD;
    float*  Cs = (float*)smraw;
    __shared__ int sPid[128];

    int e = blockIdx.z;
    int count = g_cnt[e];
    int mBase = blockIdx.x * 128;          // x = mtile
    if (mBase >= count) return;
    int colBase = blockIdx.y * 128;

    int tx = threadIdx.x;
    if (tx < 128) {
        int r = mBase + tx;
        sPid[tx] = (r < count) ? g_rows[e * T_TOK + r] : -1;
    }
    __syncthreads();

    const __half* B = g_wdh + (size_t)e * INTER * H_DIM;
    int warp = tx >> 5, wm = warp >> 1, wn = warp & 1;

    HFragC c[2][4];
#pragma unroll
    for (int mi = 0; mi < 2; mi++)
#pragma unroll
        for (int ni = 0; ni < 4; ni++) wmma::fill_fragment(c[mi][ni], 0.f);

    int arow = tx >> 1, acol = (tx & 1) * 8;
    int brow = tx >> 4, bcol = (tx & 15) * 8;
    int pidA = sPid[arow];
    bool valid = (pidA >= 0);
    const __half* aP = g_acth + (valid ? (size_t)pidA * INTER : 0) + acol;
    const __half* bP = B + (size_t)brow * H_DIM + colBase + bcol;
    const int nt = INTER >> 4;

    cp16(&As[arow * AH_LD + acol], aP, valid);
    cp16(&Bs[brow * BH_LD + bcol], bP, true);
    cp_commit();

    for (int t = 0; t < nt; t++) {
        int cur = t & 1, nxt = cur ^ 1;
        if (t + 1 < nt) {
            cp16(&As[nxt * 128 * AH_LD + arow * AH_LD + acol], aP + (t + 1) * 16, valid);
            cp16(&Bs[nxt * 16 * BH_LD + brow * BH_LD + bcol], bP + (size_t)(t + 1) * 16 * H_DIM, true);
            cp_commit();
            cp_wait1();
        } else cp_wait0();
        __syncthreads();
        HFragA a[2]; HFragB b[4];
#pragma unroll
        for (int mi = 0; mi < 2; mi++)
            wmma::load_matrix_sync(a[mi], &As[cur * 128 * AH_LD + (wm * 32 + mi * 16) * AH_LD], AH_LD);
#pragma unroll
        for (int ni = 0; ni < 4; ni++)
            wmma::load_matrix_sync(b[ni], &Bs[cur * 16 * BH_LD + wn * 64 + ni * 16], BH_LD);
#pragma unroll
        for (int mi = 0; mi < 2; mi++)
#pragma unroll
            for (int ni = 0; ni < 4; ni++)
                wmma::mma_sync(c[mi][ni], a[mi], b[ni], c[mi][ni]);
        __syncthreads();
    }

#pragma unroll
    for (int mi = 0; mi < 2; mi++)
#pragma unroll
        for (int ni = 0; ni < 4; ni++)
            wmma::store_matrix_sync(&Cs[(wm * 32 + mi * 16) * CS_LD + wn * 64 + ni * 16],
                                    c[mi][ni], CS_LD, wmma::mem_row_major);
    __syncthreads();

    int orow = tx >> 1, ocol = (tx & 1) * 64;
    int pid = sPid[orow];
    if (pid >= 0) {
        float scale = g_pairw[pid];
        float* dst = g_ypair + (size_t)pid * H_DIM + colBase + ocol;
        const float* src = &Cs[orow * CS_LD + ocol];
#pragma unroll
        for (int i = 0; i < 16; i++) {
            float4 v = *(const float4*)(src + i * 4);
            v.x *= scale; v.y *= scale; v.z *= scale; v.w *= scale;
            *(float4*)(dst + i * 4) = v;
        }
    }
}

// ---------------- block reduce ----------------
__device__ __forceinline__ float blockReduceSum(float v)
{
    __shared__ float red[8];
    int lane = threadIdx.x & 31, warp = threadIdx.x >> 5;
#pragma unroll
    for (int o = 16; o; o >>= 1) v += __shfl_xor_sync(0xffffffffu, v, o);
    if (lane == 0) red[warp] = v;
    __syncthreads();
    if (warp == 0) {
        float t = (lane < 8) ? red[lane] : 0.f;
#pragma unroll
        for (int o = 4; o; o >>= 1) t += __shfl_xor_sync(0xffffffffu, t, o);
        if (lane == 0) red[0] = t;
    }
    __syncthreads();
    return red[0];
}

// ---------------- add + rmsnorm ----------------
__global__ __launch_bounds__(256) void addnorm_kernel(
    const float* __restrict__ a, const float* __restrict__ b)
{
    int t = blockIdx.x, tx = threadIdx.x;
    const float* ap = a + (size_t)t * H_DIM;
    const float* bp = b + (size_t)t * H_DIM;
    float v[4]; float ss = 0.f;
#pragma unroll
    for (int j = 0; j < 4; j++) {
        int i = tx + j * 256;
        float x = ap[i] + bp[i];
        v[j] = x; ss += x * x;
    }
    float tot = blockReduceSum(ss);
    float scale = rsqrtf(tot * (1.f / H_DIM) + 1e-5f);
    float* op = g_hs + (size_t)t * H_DIM;
    __half* oh = g_hsh + (size_t)t * H_DIM;
#pragma unroll
    for (int j = 0; j < 4; j++) {
        int i = tx + j * 256;
        float x = v[j] * scale;
        op[i] = x;
        oh[i] = __float2half_rn(x);
    }
}

// ---------------- routing ----------------
__global__ void zerocnt_kernel() { if (threadIdx.x < NEXP) g_cnt[threadIdx.x] = 0; }

__global__ void route_kernel(const float* __restrict__ wg)
{
    int t = blockIdx.x, lane = threadIdx.x;
    float p[8];
#pragma unroll
    for (int e = 0; e < 8; e++) p[e] = 0.f;
    const float* x = g_hs + (size_t)t * H_DIM;
    for (int h = lane; h < H_DIM; h += 32) {
        float xv = x[h];
#pragma unroll
        for (int e = 0; e < 8; e++) p[e] += xv * wg[h * 8 + e];
    }
#pragma unroll
    for (int e = 0; e < 8; e++)
#pragma unroll
        for (int o = 16; o; o >>= 1) p[e] += __shfl_xor_sync(0xffffffffu, p[e], o);

    if (lane == 0) {
        int e0 = 0; float l0 = p[0];
        for (int e = 1; e < 8; e++) if (p[e] > l0) { l0 = p[e]; e0 = e; }
        int e1 = -1; float l1 = -1e30f;
        for (int e = 0; e < 8; e++) if (e != e0 && p[e] > l1) { l1 = p[e]; e1 = e; }
        float w0 = 1.f / (1.f + expf(l1 - l0));
        float w1 = 1.f - w0;
        int pos0 = atomicAdd(&g_cnt[e0], 1);
        g_rows[e0 * T_TOK + pos0] = t * 2;
        g_pairw[t * 2] = w0;
        int pos1 = atomicAdd(&g_cnt[e1], 1);
        g_rows[e1 * T_TOK + pos1] = t * 2 + 1;
        g_pairw[t * 2 + 1] = w1;
    }
}

// ---------------- final rmsnorm ----------------
__global__ __launch_bounds__(256) void final_kernel(float* __restrict__ out)
{
    int t = blockIdx.x, tx = threadIdx.x;
    const float* hs = g_hs + (size_t)t * H_DIM;
    const float* y0 = g_ypair + (size_t)(t * 2) * H_DIM;
    const float* y1 = y0 + H_DIM;
    float v[4]; float ss = 0.f;
#pragma unroll
    for (int j = 0; j < 4; j++) {
        int i = tx + j * 256;
        float x = hs[i] + y0[i] + y1[i];
        v[j] = x; ss += x * x;
    }
    float tot = blockReduceSum(ss);
    float scale = rsqrtf(tot * (1.f / H_DIM) + 1e-5f);
    float* op = out + (size_t)t * H_DIM;
#pragma unroll
    for (int j = 0; j < 4; j++) op[tx + j * 256] = v[j] * scale;
}

// ---------------- launch ----------------
extern "C" void kernel_launch(void* const* d_in, const int* in_sizes, int n_in,
                              void* d_out, int out_size)
{
    const float* hidden = (const float*)d_in[0];
    const float* cosp   = (const float*)d_in[1];
    const float* sinp   = (const float*)d_in[2];
    const float* w_qkv  = (const float*)d_in[3];
    const float* w_o    = (const float*)d_in[4];
    const float* w_gate = (const float*)d_in[5];
    const float* w_gu   = (const float*)d_in[6];
    const float* w_down = (const float*)d_in[7];
    float* out = (float*)d_out;

    float*  qkv_ptr;  cudaGetSymbolAddress((void**)&qkv_ptr,  g_qkv);
    float*  tmp_ptr;  cudaGetSymbolAddress((void**)&tmp_ptr,  g_tmp);
    __half* hidh_ptr; cudaGetSymbolAddress((void**)&hidh_ptr, g_hidh);
    __half* ctxh_ptr; cudaGetSymbolAddress((void**)&ctxh_ptr, g_ctxh);
    __half* wqkvh_ptr;cudaGetSymbolAddress((void**)&wqkvh_ptr,g_wqkvh);
    __half* woh_ptr;  cudaGetSymbolAddress((void**)&woh_ptr,  g_woh);
    __half* wguh_ptr; cudaGetSymbolAddress((void**)&wguh_ptr, g_wguh);
    __half* wdh_ptr;  cudaGetSymbolAddress((void**)&wdh_ptr,  g_wdh);

    const int GU_SMEM   = 128 * GC_LD * 4;   // 34.8 KB
    const int DOWN_SMEM = 128 * CS_LD * 4;   // 67.6 KB
    const int ATT_SMEM  = 90624;             // fused attention (2 CTAs/SM)
    static bool attrs_set = false;
    if (!attrs_set) {
        cudaFuncSetAttribute(moe_gateup_kernel, cudaFuncAttributeMaxDynamicSharedMemorySize, GU_SMEM);
        cudaFuncSetAttribute(moe_down_kernel,   cudaFuncAttributeMaxDynamicSharedMemorySize, DOWN_SMEM);
        cudaFuncSetAttribute(attn_fused_kernel, cudaFuncAttributeMaxDynamicSharedMemorySize, ATT_SMEM);
        attrs_set = true;
    }

    auto cvt = [](const float* in, __half* out, size_t n) {
        cvt_kernel<<<(unsigned)((n / 4 + 255) / 256), 256>>>(in, out, n);
    };

    // 0. f32 -> f16 conversions
    cvt(hidden, hidh_ptr,  (size_t)T_TOK * H_DIM);
    cvt(w_qkv,  wqkvh_ptr, (size_t)H_DIM * 3 * H_DIM);
    cvt(w_o,    woh_ptr,   (size_t)H_DIM * H_DIM);
    cvt(w_gu,   wguh_ptr,  (size_t)NEXP * H_DIM * GU2);
    cvt(w_down, wdh_ptr,   (size_t)NEXP * INTER * H_DIM);

    // 1. QKV projection
    gemm_f16_kernel<<<dim3(3072 / 128, 2048 / 128), 256>>>(hidh_ptr, wqkvh_ptr, qkv_ptr, 2048, 3072, 1024);

    // 2. RoPE -> f16 qkv
    rope_kernel<<<(T_TOK * NHEAD * 32) / 256, 256>>>(cosp, sinp);

    // 3. fused flash attention (64-row tiles, 2 CTAs/SM) -> g_ctxh
    attn_fused_kernel<<<dim3(16, 32), 256, ATT_SMEM>>>();

    // 4. O projection
    gemm_f16_kernel<<<dim3(1024 / 128, 2048 / 128), 256>>>(ctxh_ptr, woh_ptr, tmp_ptr, 2048, 1024, 1024);

    // 5. hs = rmsnorm(x + attn_out)
    addnorm_kernel<<<T_TOK, 256>>>(hidden, tmp_ptr);

    // 6. routing
    zerocnt_kernel<<<1, 32>>>();
    route_kernel<<<T_TOK, 32>>>(w_gate);

    // 7. fused gate_up + silu -> g_acth   (x = mtile for L2 B-reuse)
    moe_gateup_kernel<<<dim3(2048 / 128, INTER / 64, NEXP), 256, GU_SMEM>>>();

    // 8. down proj (weighted) -> g_ypair  (x = mtile)
    moe_down_kernel<<<dim3(2048 / 128, 1024 / 128, NEXP), 256, DOWN_SMEM>>>();

    // 9. out = rmsnorm(hs + mixed)
    final_kernel<<<T_TOK, 256>>>(out);
}

// round 15
// speedup vs baseline: 1.0168x; 1.0168x over previous
#include <cuda_runtime.h>
#include <mma.h>
#include <cuda_fp16.h>
#include <math.h>
#include <cstdint>

using namespace nvcuda;

// ---------------- problem constants ----------------
#define T_TOK 2048
#define S_LEN 1024
#define H_DIM 1024
#define NHEAD 16
#define HD    64
#define NEXP  8
#define INTER 2816
#define GU2   (2*INTER)

// ---------------- device scratch ----------------
__device__ float  g_qkv [(size_t)T_TOK * 3 * H_DIM];
__device__ __half g_qkvh[(size_t)T_TOK * 3 * H_DIM];
__device__ __half g_ctxh[(size_t)T_TOK * H_DIM];
__device__ float  g_tmp [(size_t)T_TOK * H_DIM];
__device__ float  g_hs  [(size_t)T_TOK * H_DIM];
__device__ __half g_hsh [(size_t)T_TOK * H_DIM];
__device__ __half g_acth[(size_t)T_TOK * 2 * INTER];
__device__ float  g_ypair[(size_t)T_TOK * 2 * H_DIM];
__device__ __half g_hidh[(size_t)T_TOK * H_DIM];
__device__ __half g_wqkvh[(size_t)H_DIM * 3 * H_DIM];
__device__ __half g_woh [(size_t)H_DIM * H_DIM];
__device__ float  g_pairw[T_TOK * 2];
__device__ int    g_cnt [NEXP];
__device__ int    g_rows[NEXP * T_TOK];

// ---------------- cp.async helpers ----------------
__device__ __forceinline__ void cp16(void* s, const void* g, bool pred) {
    unsigned int sa = (unsigned int)__cvta_generic_to_shared(s);
    int sz = pred ? 16 : 0;
    asm volatile("cp.async.cg.shared.global [%0], [%1], 16, %2;\n" :: "r"(sa), "l"(g), "r"(sz));
}
__device__ __forceinline__ void cp_commit() { asm volatile("cp.async.commit_group;\n"); }
__device__ __forceinline__ void cp_wait1()  { asm volatile("cp.async.wait_group 1;\n" ::: "memory"); }
__device__ __forceinline__ void cp_wait0()  { asm volatile("cp.async.wait_group 0;\n" ::: "memory"); }

// pack 8 f32 -> 8 f16 and store as uint4
__device__ __forceinline__ void st8h(__half* dst, float4 r0, float4 r1) {
    __half2 h0 = __floats2half2_rn(r0.x, r0.y);
    __half2 h1 = __floats2half2_rn(r0.z, r0.w);
    __half2 h2 = __floats2half2_rn(r1.x, r1.y);
    __half2 h3 = __floats2half2_rn(r1.z, r1.w);
    uint4 pk;
    pk.x = *reinterpret_cast<unsigned*>(&h0);
    pk.y = *reinterpret_cast<unsigned*>(&h1);
    pk.z = *reinterpret_cast<unsigned*>(&h2);
    pk.w = *reinterpret_cast<unsigned*>(&h3);
    *reinterpret_cast<uint4*>(dst) = pk;
}

// half-precision shared layouts (elements)
#define AH_LD 24
#define BH_LD 136
#define VH_LD 72
// f32 epilogue stages
#define CS_LD 132
#define GC_LD 68
// fused attention layouts
#define FA_QLD 72
#define FA_SLD 68

typedef wmma::fragment<wmma::matrix_a, 16, 16, 16, __half, wmma::row_major> HFragA;
typedef wmma::fragment<wmma::matrix_b, 16, 16, 16, __half, wmma::row_major> HFragB;
typedef wmma::fragment<wmma::matrix_b, 16, 16, 16, __half, wmma::col_major> HFragBc;
typedef wmma::fragment<wmma::accumulator, 16, 16, 16, float> HFragC;

// ---------------- f32 -> f16 conversion ----------------
__global__ void cvt_kernel(const float* __restrict__ in, __half* __restrict__ out, size_t n)
{
    size_t i = ((size_t)blockIdx.x * blockDim.x + threadIdx.x) * 4;
    if (i >= n) return;
    float4 v = *(const float4*)(in + i);
    *(__half2*)(out + i)     = __floats2half2_rn(v.x, v.y);
    *(__half2*)(out + i + 2) = __floats2half2_rn(v.z, v.w);
}

// ================= plain FP16 GEMM: C_f32[M,N] = A_h[M,K] @ B_h[K,N], BK=16 =================
__global__ __launch_bounds__(256, 2) void gemm_f16_kernel(
    const __half* __restrict__ A, const __half* __restrict__ B,
    float* __restrict__ C, int M, int N, int K)
{
    __shared__ __half As[2][128 * AH_LD];
    __shared__ __half Bs[2][16 * BH_LD];

    int tx = threadIdx.x;
    int rowBase = blockIdx.y * 128;
    int colBase = blockIdx.x * 128;
    int warp = tx >> 5, wm = warp >> 1, wn = warp & 1;

    HFragC c[2][4];
#pragma unroll
    for (int mi = 0; mi < 2; mi++)
#pragma unroll
        for (int ni = 0; ni < 4; ni++) wmma::fill_fragment(c[mi][ni], 0.f);

    int arow = tx >> 1, acol = (tx & 1) * 8;
    int brow = tx >> 4, bcol = (tx & 15) * 8;
    const __half* aP = A + (size_t)(rowBase + arow) * K + acol;
    const __half* bP = B + (size_t)brow * N + colBase + bcol;
    int nt = K >> 4;

    cp16(&As[0][arow * AH_LD + acol], aP, true);
    cp16(&Bs[0][brow * BH_LD + bcol], bP, true);
    cp_commit();

    for (int t = 0; t < nt; t++) {
        int cur = t & 1, nxt = cur ^ 1;
        if (t + 1 < nt) {
            cp16(&As[nxt][arow * AH_LD + acol], aP + (t + 1) * 16, true);
            cp16(&Bs[nxt][brow * BH_LD + bcol], bP + (size_t)(t + 1) * 16 * N, true);
            cp_commit();
            cp_wait1();
        } else cp_wait0();
        __syncthreads();
        HFragA a[2]; HFragB b[4];
#pragma unroll
        for (int mi = 0; mi < 2; mi++)
            wmma::load_matrix_sync(a[mi], &As[cur][(wm * 32 + mi * 16) * AH_LD], AH_LD);
#pragma unroll
        for (int ni = 0; ni < 4; ni++)
            wmma::load_matrix_sync(b[ni], &Bs[cur][wn * 64 + ni * 16], BH_LD);
#pragma unroll
        for (int mi = 0; mi < 2; mi++)
#pragma unroll
            for (int ni = 0; ni < 4; ni++)
                wmma::mma_sync(c[mi][ni], a[mi], b[ni], c[mi][ni]);
        __syncthreads();
    }
#pragma unroll
    for (int mi = 0; mi < 2; mi++)
#pragma unroll
        for (int ni = 0; ni < 4; ni++)
            wmma::store_matrix_sync(
                &C[(size_t)(rowBase + wm * 32 + mi * 16) * N + colBase + wn * 64 + ni * 16],
                c[mi][ni], N, wmma::mem_row_major);
}

// ================= RoPE: f32 g_qkv -> f16 g_qkvh =================
__global__ void rope_kernel(const float* __restrict__ cosp, const float* __restrict__ sinp)
{
    int idx = blockIdx.x * blockDim.x + threadIdx.x;
    if (idx >= T_TOK * NHEAD * 32) return;
    int d = idx & 31;
    int n = (idx >> 5) & 15;
    int t = idx >> 9;
    int s = t & (S_LEN - 1);
    float c1 = cosp[s * 64 + d],      s1 = sinp[s * 64 + d];
    float c2 = cosp[s * 64 + d + 32], s2 = sinp[s * 64 + d + 32];
    size_t base = (size_t)t * 3072 + n * 64 + d;
    float x1 = g_qkv[base], x2 = g_qkv[base + 32];
    g_qkvh[base]      = __float2half_rn(x1 * c1 - x2 * s1);
    g_qkvh[base + 32] = __float2half_rn(x2 * c2 + x1 * s2);
    x1 = g_qkv[base + 1024]; x2 = g_qkv[base + 1056];
    g_qkvh[base + 1024] = __float2half_rn(x1 * c1 - x2 * s1);
    g_qkvh[base + 1056] = __float2half_rn(x2 * c2 + x1 * s2);
    g_qkvh[base + 2048] = __float2half_rn(g_qkv[base + 2048]);
    g_qkvh[base + 2080] = __float2half_rn(g_qkv[base + 2080]);
}

// ================= FUSED flash attention (R12 config: 128-row tiles) =================
__global__ __launch_bounds__(256) void attn_fused_kernel()
{
    extern __shared__ char smraw[];
    __half* Qs = (__half*)smraw;
    __half* Ks = (__half*)(smraw + 18432);
    __half* Vs = (__half*)(smraw + 36864);
    __half* Ps = (__half*)(smraw + 55296);
    float*  Ss = (float*)(smraw + 73728);
    float*  Os = (float*)(smraw + 108544);
    float*  mrow = (float*)(smraw + 143360);
    float*  lrow = (float*)(smraw + 143872);

    int z = blockIdx.y;
    int b = z >> 4, h = z & 15;
    int qBase = blockIdx.x * 128;
    int tbase = b * S_LEN;
    int tx = threadIdx.x;
    int warp = tx >> 5, wm = warp >> 1, wn = warp & 1;

    {
        int r = tx >> 1, cs = (tx & 1) * 32;
        const __half* qp = g_qkvh + (size_t)(tbase + qBase + r) * 3072 + h * 64 + cs;
#pragma unroll
        for (int j = 0; j < 4; j++) cp16(&Qs[r * FA_QLD + cs + j * 8], qp + j * 8, true);
        int kr = tx >> 2, kcs = (tx & 3) * 16;
        const __half* kp = g_qkvh + (size_t)(tbase + kr) * 3072 + 1024 + h * 64 + kcs;
        cp16(&Ks[kr * FA_QLD + kcs], kp, true);
        cp16(&Ks[kr * FA_QLD + kcs + 8], kp + 8, true);
        cp16(&Vs[kr * FA_QLD + kcs], kp + 1024, true);
        cp16(&Vs[kr * FA_QLD + kcs + 8], kp + 1024 + 8, true);
        cp_commit();
    }
#pragma unroll
    for (int j = 0; j < 34; j++) Os[tx + j * 256] = 0.f;
    if (tx < 128) { mrow[tx] = -1e30f; lrow[tx] = 0.f; }
    cp_wait0();
    __syncthreads();

    const int row2 = tx >> 1, half2 = tx & 1;

    for (int t = 0; t < 16; t++) {
        int cur = t & 1, nxt = cur ^ 1;
        if (t + 1 < 16) {
            int kr = tx >> 2, kcs = (tx & 3) * 16;
            const __half* kp = g_qkvh + (size_t)(tbase + (t + 1) * 64 + kr) * 3072 + 1024 + h * 64 + kcs;
            cp16(&Ks[nxt * 64 * FA_QLD + kr * FA_QLD + kcs], kp, true);
            cp16(&Ks[nxt * 64 * FA_QLD + kr * FA_QLD + kcs + 8], kp + 8, true);
            cp16(&Vs[nxt * 64 * FA_QLD + kr * FA_QLD + kcs], kp + 1024, true);
            cp16(&Vs[nxt * 64 * FA_QLD + kr * FA_QLD + kcs + 8], kp + 1024 + 8, true);
            cp_commit();
        }

        {
            HFragC cs[2][2];
#pragma unroll
            for (int mi = 0; mi < 2; mi++)
#pragma unroll
                for (int ni = 0; ni < 2; ni++) wmma::fill_fragment(cs[mi][ni], 0.f);
#pragma unroll
            for (int kk = 0; kk < 4; kk++) {
                HFragA a[2]; HFragBc bb[2];
#pragma unroll
                for (int mi = 0; mi < 2; mi++)
                    wmma::load_matrix_sync(a[mi], &Qs[(wm * 32 + mi * 16) * FA_QLD + kk * 16], FA_QLD);
#pragma unroll
                for (int ni = 0; ni < 2; ni++)
                    wmma::load_matrix_sync(bb[ni], &Ks[cur * 64 * FA_QLD + (wn * 32 + ni * 16) * FA_QLD + kk * 16], FA_QLD);
#pragma unroll
                for (int mi = 0; mi < 2; mi++)
#pragma unroll
                    for (int ni = 0; ni < 2; ni++)
                        wmma::mma_sync(cs[mi][ni], a[mi], bb[ni], cs[mi][ni]);
            }
#pragma unroll
            for (int mi = 0; mi < 2; mi++)
#pragma unroll
                for (int ni = 0; ni < 2; ni++) {
#pragma unroll
                    for (int i = 0; i < cs[mi][ni].num_elements; i++) cs[mi][ni].x[i] *= 0.125f;
                    wmma::store_matrix_sync(&Ss[(wm * 32 + mi * 16) * FA_SLD + wn * 32 + ni * 16],
                                            cs[mi][ni], FA_SLD, wmma::mem_row_major);
                }
        }
        __syncthreads();

        {
            const float* srow = &Ss[row2 * FA_SLD + half2 * 32];
            float s[32];
            float tmax = -1e30f;
#pragma unroll
            for (int i = 0; i < 32; i++) { s[i] = srow[i]; tmax = fmaxf(tmax, s[i]); }
            tmax = fmaxf(tmax, __shfl_xor_sync(0xffffffffu, tmax, 1));
            float m_old = mrow[row2];
            float m_new = fmaxf(m_old, tmax);
            float alpha = __expf(m_old - m_new);
            float psum = 0.f;
            __half* prow = &Ps[row2 * FA_QLD + half2 * 32];
#pragma unroll
            for (int i = 0; i < 32; i += 2) {
                float p0 = __expf(s[i] - m_new);
                float p1 = __expf(s[i + 1] - m_new);
                psum += p0 + p1;
                *(__half2*)(prow + i) = __floats2half2_rn(p0, p1);
            }
            psum += __shfl_xor_sync(0xffffffffu, psum, 1);
            if (half2 == 0) {
                mrow[row2] = m_new;
                lrow[row2] = lrow[row2] * alpha + psum;
            }
            float* orow = &Os[row2 * FA_SLD + half2 * 32];
#pragma unroll
            for (int i = 0; i < 32; i++) orow[i] *= alpha;
        }
        __syncthreads();

        {
            HFragC co[2][2];
#pragma unroll
            for (int mi = 0; mi < 2; mi++)
#pragma unroll
                for (int ni = 0; ni < 2; ni++)
                    wmma::load_matrix_sync(co[mi][ni], &Os[(wm * 32 + mi * 16) * FA_SLD + wn * 32 + ni * 16],
                                           FA_SLD, wmma::mem_row_major);
#pragma unroll
            for (int kk = 0; kk < 4; kk++) {
                HFragA a[2]; HFragB bb[2];
#pragma unroll
                for (int mi = 0; mi < 2; mi++)
                    wmma::load_matrix_sync(a[mi], &Ps[(wm * 32 + mi * 16) * FA_QLD + kk * 16], FA_QLD);
#pragma unroll
                for (int ni = 0; ni < 2; ni++)
                    wmma::load_matrix_sync(bb[ni], &Vs[cur * 64 * FA_QLD + (kk * 16) * FA_QLD + wn * 32 + ni * 16], FA_QLD);
#pragma unroll
                for (int mi = 0; mi < 2; mi++)
#pragma unroll
                    for (int ni = 0; ni < 2; ni++)
                        wmma::mma_sync(co[mi][ni], a[mi], bb[ni], co[mi][ni]);
            }
#pragma unroll
            for (int mi = 0; mi < 2; mi++)
#pragma unroll
                for (int ni = 0; ni < 2; ni++)
                    wmma::store_matrix_sync(&Os[(wm * 32 + mi * 16) * FA_SLD + wn * 32 + ni * 16],
                                            co[mi][ni], FA_SLD, wmma::mem_row_major);
        }
        if (t + 1 < 16) cp_wait0();
        __syncthreads();
    }

    {
        float inv = 1.f / lrow[row2];
        const float* orow = &Os[row2 * FA_SLD + half2 * 32];
        __half* dst = g_ctxh + (size_t)(tbase + qBase + row2) * H_DIM + h * 64 + half2 * 32;
#pragma unroll
        for (int i = 0; i < 32; i += 2)
            *(__half2*)(dst + i) = __floats2half2_rn(orow[i] * inv, orow[i + 1] * inv);
    }
}

// ================= MoE gate_up fused silu — direct f32 weights, reg-staged cvt ==========
__global__ __launch_bounds__(256, 2) void moe_gateup_kernel(const float* __restrict__ Wgu)
{
    extern __shared__ char smraw[];
    __half* As = (__half*)smraw;
    __half* Bg = As + 2 * 128 * AH_LD;
    __half* Bu = Bg + 2 * 16 * VH_LD;
    float*  Cs = (float*)smraw;
    __shared__ int sPid[128];

    int e = blockIdx.z;
    int count = g_cnt[e];
    int mBase = blockIdx.y * 128;
    if (mBase >= count) return;
    int nBase = blockIdx.x * 64;

    int tx = threadIdx.x;
    if (tx < 128) {
        int r = mBase + tx;
        sPid[tx] = (r < count) ? g_rows[e * T_TOK + r] : -1;
    }
    __syncthreads();

    const float* B = Wgu + (size_t)e * H_DIM * GU2;
    int warp = tx >> 5, wm = warp >> 1, wn = warp & 1;

    HFragC cg[2][2], cu[2][2];
#pragma unroll
    for (int mi = 0; mi < 2; mi++)
#pragma unroll
        for (int ni = 0; ni < 2; ni++) { wmma::fill_fragment(cg[mi][ni], 0.f); wmma::fill_fragment(cu[mi][ni], 0.f); }

    int arow = tx >> 1, acol = (tx & 1) * 8;
    int pidA = sPid[arow];
    bool valid = (pidA >= 0);
    const __half* aP = g_hsh + (valid ? (size_t)(pidA >> 1) * H_DIM : 0) + acol;
    int btx = tx & 127;
    int brow = btx >> 3, bcol = (btx & 7) * 8;
    bool isUp = (tx >= 128);
    const float* bP = B + (size_t)brow * GU2 + nBase + bcol + (isUp ? INTER : 0);
    __half* Bdst = isUp ? Bu : Bg;
    const int nt = H_DIM >> 4;   // 64

    // prologue: B(0) via regs, A(0) via cp.async
    {
        float4 r0 = *(const float4*)bP;
        float4 r1 = *(const float4*)(bP + 4);
        cp16(&As[arow * AH_LD + acol], aP, valid);
        cp_commit();
        st8h(&Bdst[brow * VH_LD + bcol], r0, r1);
        cp_wait0();
    }
    __syncthreads();

    for (int t = 0; t < nt; t++) {
        int cur = t & 1, nxt = cur ^ 1;
        float4 r0, r1;
        if (t + 1 < nt) {
            const float* b2 = bP + (size_t)(t + 1) * 16 * GU2;
            r0 = *(const float4*)b2;
            r1 = *(const float4*)(b2 + 4);
            cp16(&As[nxt * 128 * AH_LD + arow * AH_LD + acol], aP + (t + 1) * 16, valid);
            cp_commit();
        }
        HFragA a[2];
#pragma unroll
        for (int mi = 0; mi < 2; mi++)
            wmma::load_matrix_sync(a[mi], &As[cur * 128 * AH_LD + (wm * 32 + mi * 16) * AH_LD], AH_LD);
#pragma unroll
        for (int ni = 0; ni < 2; ni++) {
            HFragB bg;
            wmma::load_matrix_sync(bg, &Bg[cur * 16 * VH_LD + wn * 32 + ni * 16], VH_LD);
#pragma unroll
            for (int mi = 0; mi < 2; mi++)
                wmma::mma_sync(cg[mi][ni], a[mi], bg, cg[mi][ni]);
            HFragB bu;
            wmma::load_matrix_sync(bu, &Bu[cur * 16 * VH_LD + wn * 32 + ni * 16], VH_LD);
#pragma unroll
            for (int mi = 0; mi < 2; mi++)
                wmma::mma_sync(cu[mi][ni], a[mi], bu, cu[mi][ni]);
        }
        __syncthreads();
        if (t + 1 < nt) {
            st8h(&Bdst[nxt * 16 * VH_LD + brow * VH_LD + bcol], r0, r1);
            cp_wait0();
        }
        __syncthreads();
    }

#pragma unroll
    for (int mi = 0; mi < 2; mi++)
#pragma unroll
        for (int ni = 0; ni < 2; ni++) {
#pragma unroll
            for (int i = 0; i < cg[mi][ni].num_elements; i++) {
                float g = cg[mi][ni].x[i];
                cg[mi][ni].x[i] = g / (1.f + __expf(-g)) * cu[mi][ni].x[i];
            }
            wmma::store_matrix_sync(&Cs[(wm * 32 + mi * 16) * GC_LD + wn * 32 + ni * 16],
                                    cg[mi][ni], GC_LD, wmma::mem_row_major);
        }
    __syncthreads();

    int orow = tx >> 1, ocol = (tx & 1) * 32;
    int pid = sPid[orow];
    if (pid >= 0) {
        __half* dst = g_acth + (size_t)pid * INTER + nBase + ocol;
        const float* src = &Cs[orow * GC_LD + ocol];
#pragma unroll
        for (int i = 0; i < 16; i++)
            *(__half2*)(dst + i * 2) = __floats2half2_rn(src[i * 2], src[i * 2 + 1]);
    }
}

// ================= MoE down — direct f32 weights, reg-staged cvt =================
__global__ __launch_bounds__(256, 2) void moe_down_kernel(const float* __restrict__ Wd)
{
    extern __shared__ char smraw[];
    __half* As = (__half*)smraw;
    __half* Bs = As + 2 * 128 * AH_LD;
    float*  Cs = (float*)smraw;
    __shared__ int sPid[128];

    int e = blockIdx.z;
    int count = g_cnt[e];
    int mBase = blockIdx.y * 128;
    if (mBase >= count) return;
    int colBase = blockIdx.x * 128;

    int tx = threadIdx.x;
    if (tx < 128) {
        int r = mBase + tx;
        sPid[tx] = (r < count) ? g_rows[e * T_TOK + r] : -1;
    }
    __syncthreads();

    const float* B = Wd + (size_t)e * INTER * H_DIM;
    int warp = tx >> 5, wm = warp >> 1, wn = warp & 1;

    HFragC c[2][4];
#pragma unroll
    for (int mi = 0; mi < 2; mi++)
#pragma unroll
        for (int ni = 0; ni < 4; ni++) wmma::fill_fragment(c[mi][ni], 0.f);

    int arow = tx >> 1, acol = (tx & 1) * 8;
    int brow = tx >> 4, bcol = (tx & 15) * 8;
    int pidA = sPid[arow];
    bool valid = (pidA >= 0);
    const __half* aP = g_acth + (valid ? (size_t)pidA * INTER : 0) + acol;
    const float* bP = B + (size_t)brow * H_DIM + colBase + bcol;
    const int nt = INTER >> 4;   // 176

    {
        float4 r0 = *(const float4*)bP;
        float4 r1 = *(const float4*)(bP + 4);
        cp16(&As[arow * AH_LD + acol], aP, valid);
        cp_commit();
        st8h(&Bs[brow * BH_LD + bcol], r0, r1);
        cp_wait0();
    }
    __syncthreads();

    for (int t = 0; t < nt; t++) {
        int cur = t & 1, nxt = cur ^ 1;
        float4 r0, r1;
        if (t + 1 < nt) {
            const float* b2 = bP + (size_t)(t + 1) * 16 * H_DIM;
            r0 = *(const float4*)b2;
            r1 = *(const float4*)(b2 + 4);
            cp16(&As[nxt * 128 * AH_LD + arow * AH_LD + acol], aP + (t + 1) * 16, valid);
            cp_commit();
        }
        HFragA a[2]; HFragB b[4];
#pragma unroll
        for (int mi = 0; mi < 2; mi++)
            wmma::load_matrix_sync(a[mi], &As[cur * 128 * AH_LD + (wm * 32 + mi * 16) * AH_LD], AH_LD);
#pragma unroll
        for (int ni = 0; ni < 4; ni++)
            wmma::load_matrix_sync(b[ni], &Bs[cur * 16 * BH_LD + wn * 64 + ni * 16], BH_LD);
#pragma unroll
        for (int mi = 0; mi < 2; mi++)
#pragma unroll
            for (int ni = 0; ni < 4; ni++)
                wmma::mma_sync(c[mi][ni], a[mi], b[ni], c[mi][ni]);
        __syncthreads();
        if (t + 1 < nt) {
            st8h(&Bs[nxt * 16 * BH_LD + brow * BH_LD + bcol], r0, r1);
            cp_wait0();
        }
        __syncthreads();
    }

#pragma unroll
    for (int mi = 0; mi < 2; mi++)
#pragma unroll
        for (int ni = 0; ni < 4; ni++)
            wmma::store_matrix_sync(&Cs[(wm * 32 + mi * 16) * CS_LD + wn * 64 + ni * 16],
                                    c[mi][ni], CS_LD, wmma::mem_row_major);
    __syncthreads();

    int orow = tx >> 1, ocol = (tx & 1) * 64;
    int pid = sPid[orow];
    if (pid >= 0) {
        float scale = g_pairw[pid];
        float* dst = g_ypair + (size_t)pid * H_DIM + colBase + ocol;
        const float* src = &Cs[orow * CS_LD + ocol];
#pragma unroll
        for (int i = 0; i < 16; i++) {
            float4 v = *(const float4*)(src + i * 4);
            v.x *= scale; v.y *= scale; v.z *= scale; v.w *= scale;
            *(float4*)(dst + i * 4) = v;
        }
    }
}

// ---------------- block reduce ----------------
__device__ __forceinline__ float blockReduceSum(float v)
{
    __shared__ float red[8];
    int lane = threadIdx.x & 31, warp = threadIdx.x >> 5;
#pragma unroll
    for (int o = 16; o; o >>= 1) v += __shfl_xor_sync(0xffffffffu, v, o);
    if (lane == 0) red[warp] = v;
    __syncthreads();
    if (warp == 0) {
        float t = (lane < 8) ? red[lane] : 0.f;
#pragma unroll
        for (int o = 4; o; o >>= 1) t += __shfl_xor_sync(0xffffffffu, t, o);
        if (lane == 0) red[0] = t;
    }
    __syncthreads();
    return red[0];
}

// ---------------- add + rmsnorm ----------------
__global__ __launch_bounds__(256) void addnorm_kernel(
    const float* __restrict__ a, const float* __restrict__ b)
{
    int t = blockIdx.x, tx = threadIdx.x;
    const float* ap = a + (size_t)t * H_DIM;
    const float* bp = b + (size_t)t * H_DIM;
    float v[4]; float ss = 0.f;
#pragma unroll
    for (int j = 0; j < 4; j++) {
        int i = tx + j * 256;
        float x = ap[i] + bp[i];
        v[j] = x; ss += x * x;
    }
    float tot = blockReduceSum(ss);
    float scale = rsqrtf(tot * (1.f / H_DIM) + 1e-5f);
    float* op = g_hs + (size_t)t * H_DIM;
    __half* oh = g_hsh + (size_t)t * H_DIM;
#pragma unroll
    for (int j = 0; j < 4; j++) {
        int i = tx + j * 256;
        float x = v[j] * scale;
        op[i] = x;
        oh[i] = __float2half_rn(x);
    }
}

// ---------------- routing ----------------
__global__ void zerocnt_kernel() { if (threadIdx.x < NEXP) g_cnt[threadIdx.x] = 0; }

__global__ void route_kernel(const float* __restrict__ wg)
{
    int t = blockIdx.x, lane = threadIdx.x;
    float p[8];
#pragma unroll
    for (int e = 0; e < 8; e++) p[e] = 0.f;
    const float* x = g_hs + (size_t)t * H_DIM;
    for (int h = lane; h < H_DIM; h += 32) {
        float xv = x[h];
#pragma unroll
        for (int e = 0; e < 8; e++) p[e] += xv * wg[h * 8 + e];
    }
#pragma unroll
    for (int e = 0; e < 8; e++)
#pragma unroll
        for (int o = 16; o; o >>= 1) p[e] += __shfl_xor_sync(0xffffffffu, p[e], o);

    if (lane == 0) {
        int e0 = 0; float l0 = p[0];
        for (int e = 1; e < 8; e++) if (p[e] > l0) { l0 = p[e]; e0 = e; }
        int e1 = -1; float l1 = -1e30f;
        for (int e = 0; e < 8; e++) if (e != e0 && p[e] > l1) { l1 = p[e]; e1 = e; }
        float w0 = 1.f / (1.f + expf(l1 - l0));
        float w1 = 1.f - w0;
        int pos0 = atomicAdd(&g_cnt[e0], 1);
        g_rows[e0 * T_TOK + pos0] = t * 2;
        g_pairw[t * 2] = w0;
        int pos1 = atomicAdd(&g_cnt[e1], 1);
        g_rows[e1 * T_TOK + pos1] = t * 2 + 1;
        g_pairw[t * 2 + 1] = w1;
    }
}

// ---------------- final rmsnorm ----------------
__global__ __launch_bounds__(256) void final_kernel(float* __restrict__ out)
{
    int t = blockIdx.x, tx = threadIdx.x;
    const float* hs = g_hs + (size_t)t * H_DIM;
    const float* y0 = g_ypair + (size_t)(t * 2) * H_DIM;
    const float* y1 = y0 + H_DIM;
    float v[4]; float ss = 0.f;
#pragma unroll
    for (int j = 0; j < 4; j++) {
        int i = tx + j * 256;
        float x = hs[i] + y0[i] + y1[i];
        v[j] = x; ss += x * x;
    }
    float tot = blockReduceSum(ss);
    float scale = rsqrtf(tot * (1.f / H_DIM) + 1e-5f);
    float* op = out + (size_t)t * H_DIM;
#pragma unroll
    for (int j = 0; j < 4; j++) op[tx + j * 256] = v[j] * scale;
}

// ---------------- launch ----------------
extern "C" void kernel_launch(void* const* d_in, const int* in_sizes, int n_in,
                              void* d_out, int out_size)
{
    const float* hidden = (const float*)d_in[0];
    const float* cosp   = (const float*)d_in[1];
    const float* sinp   = (const float*)d_in[2];
    const float* w_qkv  = (const float*)d_in[3];
    const float* w_o    = (const float*)d_in[4];
    const float* w_gate = (const float*)d_in[5];
    const float* w_gu   = (const float*)d_in[6];
    const float* w_down = (const float*)d_in[7];
    float* out = (float*)d_out;

    float*  qkv_ptr;  cudaGetSymbolAddress((void**)&qkv_ptr,  g_qkv);
    float*  tmp_ptr;  cudaGetSymbolAddress((void**)&tmp_ptr,  g_tmp);
    __half* hidh_ptr; cudaGetSymbolAddress((void**)&hidh_ptr, g_hidh);
    __half* ctxh_ptr; cudaGetSymbolAddress((void**)&ctxh_ptr, g_ctxh);
    __half* wqkvh_ptr;cudaGetSymbolAddress((void**)&wqkvh_ptr,g_wqkvh);
    __half* woh_ptr;  cudaGetSymbolAddress((void**)&woh_ptr,  g_woh);

    const int GU_SMEM   = 128 * GC_LD * 4;   // 34.8 KB
    const int DOWN_SMEM = 128 * CS_LD * 4;   // 67.6 KB
    const int ATT_SMEM  = 144384;
    static bool attrs_set = false;
    if (!attrs_set) {
        cudaFuncSetAttribute(moe_gateup_kernel, cudaFuncAttributeMaxDynamicSharedMemorySize, GU_SMEM);
        cudaFuncSetAttribute(moe_down_kernel,   cudaFuncAttributeMaxDynamicSharedMemorySize, DOWN_SMEM);
        cudaFuncSetAttribute(attn_fused_kernel, cudaFuncAttributeMaxDynamicSharedMemorySize, ATT_SMEM);
        attrs_set = true;
    }

    auto cvt = [](const float* in, __half* out, size_t n) {
        cvt_kernel<<<(unsigned)((n / 4 + 255) / 256), 256>>>(in, out, n);
    };

    // 0. f32 -> f16 conversions (small tensors only; MoE weights read f32 directly)
    cvt(hidden, hidh_ptr,  (size_t)T_TOK * H_DIM);
    cvt(w_qkv,  wqkvh_ptr, (size_t)H_DIM * 3 * H_DIM);
    cvt(w_o,    woh_ptr,   (size_t)H_DIM * H_DIM);

    // 1. QKV projection
    gemm_f16_kernel<<<dim3(3072 / 128, 2048 / 128), 256>>>(hidh_ptr, wqkvh_ptr, qkv_ptr, 2048, 3072, 1024);

    // 2. RoPE -> f16 qkv
    rope_kernel<<<(T_TOK * NHEAD * 32) / 256, 256>>>(cosp, sinp);

    // 3. fused flash attention -> g_ctxh
    attn_fused_kernel<<<dim3(8, 32), 256, ATT_SMEM>>>();

    // 4. O projection
    gemm_f16_kernel<<<dim3(1024 / 128, 2048 / 128), 256>>>(ctxh_ptr, woh_ptr, tmp_ptr, 2048, 1024, 1024);

    // 5. hs = rmsnorm(x + attn_out)
    addnorm_kernel<<<T_TOK, 256>>>(hidden, tmp_ptr);

    // 6. routing
    zerocnt_kernel<<<1, 32>>>();
    route_kernel<<<T_TOK, 32>>>(w_gate);

    // 7. fused gate_up + silu -> g_acth (f32 weights direct)
    moe_gateup_kernel<<<dim3(INTER / 64, 2048 / 128, NEXP), 256, GU_SMEM>>>(w_gu);

    // 8. down proj (weighted) -> g_ypair (f32 weights direct)
    moe_down_kernel<<<dim3(1024 / 128, 2048 / 128, NEXP), 256, DOWN_SMEM>>>(w_down);

    // 9. out = rmsnorm(hs + mixed)
    final_kernel<<<T_TOK, 256>>>(out);
}

// round 16
// speedup vs baseline: 1.0231x; 1.0062x over previous
#include <cuda_runtime.h>
#include <mma.h>
#include <cuda_fp16.h>
#include <math.h>
#include <cstdint>

using namespace nvcuda;

// ---------------- problem constants ----------------
#define T_TOK 2048
#define S_LEN 1024
#define H_DIM 1024
#define NHEAD 16
#define HD    64
#define NEXP  8
#define INTER 2816
#define GU2   (2*INTER)

// ---------------- device scratch ----------------
__device__ float  g_qkv [(size_t)T_TOK * 3 * H_DIM];
__device__ __half g_qkvh[(size_t)T_TOK * 3 * H_DIM];
__device__ __half g_ctxh[(size_t)T_TOK * H_DIM];
__device__ float  g_tmp [(size_t)T_TOK * H_DIM];
__device__ float  g_hs  [(size_t)T_TOK * H_DIM];
__device__ __half g_hsh [(size_t)T_TOK * H_DIM];
__device__ __half g_acth[(size_t)T_TOK * 2 * INTER];
__device__ float  g_ypair[(size_t)T_TOK * 2 * H_DIM];
__device__ __half g_hidh[(size_t)T_TOK * H_DIM];
__device__ __half g_wqkvh[(size_t)H_DIM * 3 * H_DIM];
__device__ __half g_woh [(size_t)H_DIM * H_DIM];
__device__ float  g_pairw[T_TOK * 2];
__device__ int    g_cnt [NEXP];
__device__ int    g_rows[NEXP * T_TOK];

// ---------------- cp.async helpers ----------------
__device__ __forceinline__ void cp16(void* s, const void* g, bool pred) {
    unsigned int sa = (unsigned int)__cvta_generic_to_shared(s);
    int sz = pred ? 16 : 0;
    asm volatile("cp.async.cg.shared.global [%0], [%1], 16, %2;\n" :: "r"(sa), "l"(g), "r"(sz));
}
__device__ __forceinline__ void cp_commit() { asm volatile("cp.async.commit_group;\n"); }
__device__ __forceinline__ void cp_wait1()  { asm volatile("cp.async.wait_group 1;\n" ::: "memory"); }
__device__ __forceinline__ void cp_wait0()  { asm volatile("cp.async.wait_group 0;\n" ::: "memory"); }

// pack 8 f32 -> 8 f16 and store as uint4
__device__ __forceinline__ void st8h(__half* dst, float4 r0, float4 r1) {
    __half2 h0 = __floats2half2_rn(r0.x, r0.y);
    __half2 h1 = __floats2half2_rn(r0.z, r0.w);
    __half2 h2 = __floats2half2_rn(r1.x, r1.y);
    __half2 h3 = __floats2half2_rn(r1.z, r1.w);
    uint4 pk;
    pk.x = *reinterpret_cast<unsigned*>(&h0);
    pk.y = *reinterpret_cast<unsigned*>(&h1);
    pk.z = *reinterpret_cast<unsigned*>(&h2);
    pk.w = *reinterpret_cast<unsigned*>(&h3);
    *reinterpret_cast<uint4*>(dst) = pk;
}

// shared layouts (elements)
#define A32_LD 40    // A stage: 128 x 32 halves (+pad)
#define BH_LD 136    // B stage: 32 x 128 halves (+pad)
#define VH_LD 72     // gate/up B stage: 32 x 64 halves (+pad)
// f32 epilogue stages
#define CS_LD 132
#define GC_LD 68
// fused attention layouts
#define FA_QLD 72
#define FA_SLD 68

typedef wmma::fragment<wmma::matrix_a, 16, 16, 16, __half, wmma::row_major> HFragA;
typedef wmma::fragment<wmma::matrix_b, 16, 16, 16, __half, wmma::row_major> HFragB;
typedef wmma::fragment<wmma::matrix_b, 16, 16, 16, __half, wmma::col_major> HFragBc;
typedef wmma::fragment<wmma::accumulator, 16, 16, 16, float> HFragC;

// ---------------- f32 -> f16 conversion ----------------
__global__ void cvt_kernel(const float* __restrict__ in, __half* __restrict__ out, size_t n)
{
    size_t i = ((size_t)blockIdx.x * blockDim.x + threadIdx.x) * 4;
    if (i >= n) return;
    float4 v = *(const float4*)(in + i);
    *(__half2*)(out + i)     = __floats2half2_rn(v.x, v.y);
    *(__half2*)(out + i + 2) = __floats2half2_rn(v.z, v.w);
}

// ================= plain FP16 GEMM: BK=32, 2-stage cp.async =================
__global__ __launch_bounds__(256, 2) void gemm_f16_kernel(
    const __half* __restrict__ A, const __half* __restrict__ B,
    float* __restrict__ C, int M, int N, int K)
{
    __shared__ __half As[2][128 * A32_LD];
    __shared__ __half Bs[2][32 * BH_LD];

    int tx = threadIdx.x;
    int rowBase = blockIdx.y * 128;
    int colBase = blockIdx.x * 128;
    int warp = tx >> 5, wm = warp >> 1, wn = warp & 1;

    HFragC c[2][4];
#pragma unroll
    for (int mi = 0; mi < 2; mi++)
#pragma unroll
        for (int ni = 0; ni < 4; ni++) wmma::fill_fragment(c[mi][ni], 0.f);

    int arow = tx >> 1, acol = (tx & 1) * 16;
    int brow = tx >> 3, bcol = (tx & 7) * 16;
    const __half* aP = A + (size_t)(rowBase + arow) * K + acol;
    const __half* bP = B + (size_t)brow * N + colBase + bcol;
    int nt = K >> 5;

    cp16(&As[0][arow * A32_LD + acol],     aP,     true);
    cp16(&As[0][arow * A32_LD + acol + 8], aP + 8, true);
    cp16(&Bs[0][brow * BH_LD + bcol],      bP,     true);
    cp16(&Bs[0][brow * BH_LD + bcol + 8],  bP + 8, true);
    cp_commit();

    for (int t = 0; t < nt; t++) {
        int cur = t & 1, nxt = cur ^ 1;
        if (t + 1 < nt) {
            const __half* a2 = aP + (t + 1) * 32;
            const __half* b2 = bP + (size_t)(t + 1) * 32 * N;
            cp16(&As[nxt][arow * A32_LD + acol],     a2,     true);
            cp16(&As[nxt][arow * A32_LD + acol + 8], a2 + 8, true);
            cp16(&Bs[nxt][brow * BH_LD + bcol],      b2,     true);
            cp16(&Bs[nxt][brow * BH_LD + bcol + 8],  b2 + 8, true);
            cp_commit();
            cp_wait1();
        } else cp_wait0();
        __syncthreads();
#pragma unroll
        for (int kk = 0; kk < 2; kk++) {
            HFragA a[2]; HFragB b[4];
#pragma unroll
            for (int mi = 0; mi < 2; mi++)
                wmma::load_matrix_sync(a[mi], &As[cur][(wm * 32 + mi * 16) * A32_LD + kk * 16], A32_LD);
#pragma unroll
            for (int ni = 0; ni < 4; ni++)
                wmma::load_matrix_sync(b[ni], &Bs[cur][(kk * 16) * BH_LD + wn * 64 + ni * 16], BH_LD);
#pragma unroll
            for (int mi = 0; mi < 2; mi++)
#pragma unroll
                for (int ni = 0; ni < 4; ni++)
                    wmma::mma_sync(c[mi][ni], a[mi], b[ni], c[mi][ni]);
        }
        __syncthreads();
    }
#pragma unroll
    for (int mi = 0; mi < 2; mi++)
#pragma unroll
        for (int ni = 0; ni < 4; ni++)
            wmma::store_matrix_sync(
                &C[(size_t)(rowBase + wm * 32 + mi * 16) * N + colBase + wn * 64 + ni * 16],
                c[mi][ni], N, wmma::mem_row_major);
}

// ================= RoPE: f32 g_qkv -> f16 g_qkvh =================
__global__ void rope_kernel(const float* __restrict__ cosp, const float* __restrict__ sinp)
{
    int idx = blockIdx.x * blockDim.x + threadIdx.x;
    if (idx >= T_TOK * NHEAD * 32) return;
    int d = idx & 31;
    int n = (idx >> 5) & 15;
    int t = idx >> 9;
    int s = t & (S_LEN - 1);
    float c1 = cosp[s * 64 + d],      s1 = sinp[s * 64 + d];
    float c2 = cosp[s * 64 + d + 32], s2 = sinp[s * 64 + d + 32];
    size_t base = (size_t)t * 3072 + n * 64 + d;
    float x1 = g_qkv[base], x2 = g_qkv[base + 32];
    g_qkvh[base]      = __float2half_rn(x1 * c1 - x2 * s1);
    g_qkvh[base + 32] = __float2half_rn(x2 * c2 + x1 * s2);
    x1 = g_qkv[base + 1024]; x2 = g_qkv[base + 1056];
    g_qkvh[base + 1024] = __float2half_rn(x1 * c1 - x2 * s1);
    g_qkvh[base + 1056] = __float2half_rn(x2 * c2 + x1 * s2);
    g_qkvh[base + 2048] = __float2half_rn(g_qkv[base + 2048]);
    g_qkvh[base + 2080] = __float2half_rn(g_qkv[base + 2080]);
}

// ================= FUSED flash attention (unchanged, 128-row tiles) =================
__global__ __launch_bounds__(256) void attn_fused_kernel()
{
    extern __shared__ char smraw[];
    __half* Qs = (__half*)smraw;
    __half* Ks = (__half*)(smraw + 18432);
    __half* Vs = (__half*)(smraw + 36864);
    __half* Ps = (__half*)(smraw + 55296);
    float*  Ss = (float*)(smraw + 73728);
    float*  Os = (float*)(smraw + 108544);
    float*  mrow = (float*)(smraw + 143360);
    float*  lrow = (float*)(smraw + 143872);

    int z = blockIdx.y;
    int b = z >> 4, h = z & 15;
    int qBase = blockIdx.x * 128;
    int tbase = b * S_LEN;
    int tx = threadIdx.x;
    int warp = tx >> 5, wm = warp >> 1, wn = warp & 1;

    {
        int r = tx >> 1, cs = (tx & 1) * 32;
        const __half* qp = g_qkvh + (size_t)(tbase + qBase + r) * 3072 + h * 64 + cs;
#pragma unroll
        for (int j = 0; j < 4; j++) cp16(&Qs[r * FA_QLD + cs + j * 8], qp + j * 8, true);
        int kr = tx >> 2, kcs = (tx & 3) * 16;
        const __half* kp = g_qkvh + (size_t)(tbase + kr) * 3072 + 1024 + h * 64 + kcs;
        cp16(&Ks[kr * FA_QLD + kcs], kp, true);
        cp16(&Ks[kr * FA_QLD + kcs + 8], kp + 8, true);
        cp16(&Vs[kr * FA_QLD + kcs], kp + 1024, true);
        cp16(&Vs[kr * FA_QLD + kcs + 8], kp + 1024 + 8, true);
        cp_commit();
    }
#pragma unroll
    for (int j = 0; j < 34; j++) Os[tx + j * 256] = 0.f;
    if (tx < 128) { mrow[tx] = -1e30f; lrow[tx] = 0.f; }
    cp_wait0();
    __syncthreads();

    const int row2 = tx >> 1, half2 = tx & 1;

    for (int t = 0; t < 16; t++) {
        int cur = t & 1, nxt = cur ^ 1;
        if (t + 1 < 16) {
            int kr = tx >> 2, kcs = (tx & 3) * 16;
            const __half* kp = g_qkvh + (size_t)(tbase + (t + 1) * 64 + kr) * 3072 + 1024 + h * 64 + kcs;
            cp16(&Ks[nxt * 64 * FA_QLD + kr * FA_QLD + kcs], kp, true);
            cp16(&Ks[nxt * 64 * FA_QLD + kr * FA_QLD + kcs + 8], kp + 8, true);
            cp16(&Vs[nxt * 64 * FA_QLD + kr * FA_QLD + kcs], kp + 1024, true);
            cp16(&Vs[nxt * 64 * FA_QLD + kr * FA_QLD + kcs + 8], kp + 1024 + 8, true);
            cp_commit();
        }

        {
            HFragC cs[2][2];
#pragma unroll
            for (int mi = 0; mi < 2; mi++)
#pragma unroll
                for (int ni = 0; ni < 2; ni++) wmma::fill_fragment(cs[mi][ni], 0.f);
#pragma unroll
            for (int kk = 0; kk < 4; kk++) {
                HFragA a[2]; HFragBc bb[2];
#pragma unroll
                for (int mi = 0; mi < 2; mi++)
                    wmma::load_matrix_sync(a[mi], &Qs[(wm * 32 + mi * 16) * FA_QLD + kk * 16], FA_QLD);
#pragma unroll
                for (int ni = 0; ni < 2; ni++)
                    wmma::load_matrix_sync(bb[ni], &Ks[cur * 64 * FA_QLD + (wn * 32 + ni * 16) * FA_QLD + kk * 16], FA_QLD);
#pragma unroll
                for (int mi = 0; mi < 2; mi++)
#pragma unroll
                    for (int ni = 0; ni < 2; ni++)
                        wmma::mma_sync(cs[mi][ni], a[mi], bb[ni], cs[mi][ni]);
            }
#pragma unroll
            for (int mi = 0; mi < 2; mi++)
#pragma unroll
                for (int ni = 0; ni < 2; ni++) {
#pragma unroll
                    for (int i = 0; i < cs[mi][ni].num_elements; i++) cs[mi][ni].x[i] *= 0.125f;
                    wmma::store_matrix_sync(&Ss[(wm * 32 + mi * 16) * FA_SLD + wn * 32 + ni * 16],
                                            cs[mi][ni], FA_SLD, wmma::mem_row_major);
                }
        }
        __syncthreads();

        {
            const float* srow = &Ss[row2 * FA_SLD + half2 * 32];
            float s[32];
            float tmax = -1e30f;
#pragma unroll
            for (int i = 0; i < 32; i++) { s[i] = srow[i]; tmax = fmaxf(tmax, s[i]); }
            tmax = fmaxf(tmax, __shfl_xor_sync(0xffffffffu, tmax, 1));
            float m_old = mrow[row2];
            float m_new = fmaxf(m_old, tmax);
            float alpha = __expf(m_old - m_new);
            float psum = 0.f;
            __half* prow = &Ps[row2 * FA_QLD + half2 * 32];
#pragma unroll
            for (int i = 0; i < 32; i += 2) {
                float p0 = __expf(s[i] - m_new);
                float p1 = __expf(s[i + 1] - m_new);
                psum += p0 + p1;
                *(__half2*)(prow + i) = __floats2half2_rn(p0, p1);
            }
            psum += __shfl_xor_sync(0xffffffffu, psum, 1);
            if (half2 == 0) {
                mrow[row2] = m_new;
                lrow[row2] = lrow[row2] * alpha + psum;
            }
            float* orow = &Os[row2 * FA_SLD + half2 * 32];
#pragma unroll
            for (int i = 0; i < 32; i++) orow[i] *= alpha;
        }
        __syncthreads();

        {
            HFragC co[2][2];
#pragma unroll
            for (int mi = 0; mi < 2; mi++)
#pragma unroll
                for (int ni = 0; ni < 2; ni++)
                    wmma::load_matrix_sync(co[mi][ni], &Os[(wm * 32 + mi * 16) * FA_SLD + wn * 32 + ni * 16],
                                           FA_SLD, wmma::mem_row_major);
#pragma unroll
            for (int kk = 0; kk < 4; kk++) {
                HFragA a[2]; HFragB bb[2];
#pragma unroll
                for (int mi = 0; mi < 2; mi++)
                    wmma::load_matrix_sync(a[mi], &Ps[(wm * 32 + mi * 16) * FA_QLD + kk * 16], FA_QLD);
#pragma unroll
                for (int ni = 0; ni < 2; ni++)
                    wmma::load_matrix_sync(bb[ni], &Vs[cur * 64 * FA_QLD + (kk * 16) * FA_QLD + wn * 32 + ni * 16], FA_QLD);
#pragma unroll
                for (int mi = 0; mi < 2; mi++)
#pragma unroll
                    for (int ni = 0; ni < 2; ni++)
                        wmma::mma_sync(co[mi][ni], a[mi], bb[ni], co[mi][ni]);
            }
#pragma unroll
            for (int mi = 0; mi < 2; mi++)
#pragma unroll
                for (int ni = 0; ni < 2; ni++)
                    wmma::store_matrix_sync(&Os[(wm * 32 + mi * 16) * FA_SLD + wn * 32 + ni * 16],
                                            co[mi][ni], FA_SLD, wmma::mem_row_major);
        }
        if (t + 1 < 16) cp_wait0();
        __syncthreads();
    }

    {
        float inv = 1.f / lrow[row2];
        const float* orow = &Os[row2 * FA_SLD + half2 * 32];
        __half* dst = g_ctxh + (size_t)(tbase + qBase + row2) * H_DIM + h * 64 + half2 * 32;
#pragma unroll
        for (int i = 0; i < 32; i += 2)
            *(__half2*)(dst + i) = __floats2half2_rn(orow[i] * inv, orow[i + 1] * inv);
    }
}

// ================= MoE gate_up fused silu — f32 weights, BK=32 =================
__global__ __launch_bounds__(256, 2) void moe_gateup_kernel(const float* __restrict__ Wgu)
{
    extern __shared__ char smraw[];
    __half* As = (__half*)smraw;                 // 2 x 128 x 40 halves (20.5 KB)
    __half* Bg = As + 2 * 128 * A32_LD;          // 2 x 32 x 72 (9.2 KB)
    __half* Bu = Bg + 2 * 32 * VH_LD;            // 2 x 32 x 72
    float*  Cs = (float*)smraw;                  // epilogue: 128 x 68 f32 (34.8 KB)
    __shared__ int sPid[128];

    int e = blockIdx.z;
    int count = g_cnt[e];
    int mBase = blockIdx.y * 128;
    if (mBase >= count) return;
    int nBase = blockIdx.x * 64;

    int tx = threadIdx.x;
    if (tx < 128) {
        int r = mBase + tx;
        sPid[tx] = (r < count) ? g_rows[e * T_TOK + r] : -1;
    }
    __syncthreads();

    const float* B = Wgu + (size_t)e * H_DIM * GU2;
    int warp = tx >> 5, wm = warp >> 1, wn = warp & 1;

    HFragC cg[2][2], cu[2][2];
#pragma unroll
    for (int mi = 0; mi < 2; mi++)
#pragma unroll
        for (int ni = 0; ni < 2; ni++) { wmma::fill_fragment(cg[mi][ni], 0.f); wmma::fill_fragment(cu[mi][ni], 0.f); }

    int arow = tx >> 1, acol = (tx & 1) * 16;
    int pidA = sPid[arow];
    bool valid = (pidA >= 0);
    const __half* aP = g_hsh + (valid ? (size_t)(pidA >> 1) * H_DIM : 0) + acol;
    int btx = tx & 127;
    int brow = btx >> 2, bcol = (btx & 3) * 16;   // 32 rows x 64 cols, 16 f32/thread
    bool isUp = (tx >= 128);
    const float* bP = B + (size_t)brow * GU2 + nBase + bcol + (isUp ? INTER : 0);
    __half* Bdst = isUp ? Bu : Bg;
    const int nt = H_DIM >> 5;   // 32

    {
        float4 r0 = *(const float4*)bP;
        float4 r1 = *(const float4*)(bP + 4);
        float4 r2 = *(const float4*)(bP + 8);
        float4 r3 = *(const float4*)(bP + 12);
        cp16(&As[arow * A32_LD + acol],     aP,     valid);
        cp16(&As[arow * A32_LD + acol + 8], aP + 8, valid);
        cp_commit();
        st8h(&Bdst[brow * VH_LD + bcol],     r0, r1);
        st8h(&Bdst[brow * VH_LD + bcol + 8], r2, r3);
        cp_wait0();
    }
    __syncthreads();

    for (int t = 0; t < nt; t++) {
        int cur = t & 1, nxt = cur ^ 1;
        float4 r0, r1, r2, r3;
        if (t + 1 < nt) {
            const float* b2 = bP + (size_t)(t + 1) * 32 * GU2;
            r0 = *(const float4*)b2;
            r1 = *(const float4*)(b2 + 4);
            r2 = *(const float4*)(b2 + 8);
            r3 = *(const float4*)(b2 + 12);
            const __half* a2 = aP + (t + 1) * 32;
            cp16(&As[nxt * 128 * A32_LD + arow * A32_LD + acol],     a2,     valid);
            cp16(&As[nxt * 128 * A32_LD + arow * A32_LD + acol + 8], a2 + 8, valid);
            cp_commit();
        }
#pragma unroll
        for (int kk = 0; kk < 2; kk++) {
            HFragA a[2];
#pragma unroll
            for (int mi = 0; mi < 2; mi++)
                wmma::load_matrix_sync(a[mi], &As[cur * 128 * A32_LD + (wm * 32 + mi * 16) * A32_LD + kk * 16], A32_LD);
#pragma unroll
            for (int ni = 0; ni < 2; ni++) {
                HFragB bg;
                wmma::load_matrix_sync(bg, &Bg[cur * 32 * VH_LD + (kk * 16) * VH_LD + wn * 32 + ni * 16], VH_LD);
#pragma unroll
                for (int mi = 0; mi < 2; mi++)
                    wmma::mma_sync(cg[mi][ni], a[mi], bg, cg[mi][ni]);
                HFragB bu;
                wmma::load_matrix_sync(bu, &Bu[cur * 32 * VH_LD + (kk * 16) * VH_LD + wn * 32 + ni * 16], VH_LD);
#pragma unroll
                for (int mi = 0; mi < 2; mi++)
                    wmma::mma_sync(cu[mi][ni], a[mi], bu, cu[mi][ni]);
            }
        }
        __syncthreads();
        if (t + 1 < nt) {
            st8h(&Bdst[nxt * 32 * VH_LD + brow * VH_LD + bcol],     r0, r1);
            st8h(&Bdst[nxt * 32 * VH_LD + brow * VH_LD + bcol + 8], r2, r3);
            cp_wait0();
        }
        __syncthreads();
    }

#pragma unroll
    for (int mi = 0; mi < 2; mi++)
#pragma unroll
        for (int ni = 0; ni < 2; ni++) {
#pragma unroll
            for (int i = 0; i < cg[mi][ni].num_elements; i++) {
                float g = cg[mi][ni].x[i];
                cg[mi][ni].x[i] = g / (1.f + __expf(-g)) * cu[mi][ni].x[i];
            }
            wmma::store_matrix_sync(&Cs[(wm * 32 + mi * 16) * GC_LD + wn * 32 + ni * 16],
                                    cg[mi][ni], GC_LD, wmma::mem_row_major);
        }
    __syncthreads();

    int orow = tx >> 1, ocol = (tx & 1) * 32;
    int pid = sPid[orow];
    if (pid >= 0) {
        __half* dst = g_acth + (size_t)pid * INTER + nBase + ocol;
        const float* src = &Cs[orow * GC_LD + ocol];
#pragma unroll
        for (int i = 0; i < 16; i++)
            *(__half2*)(dst + i * 2) = __floats2half2_rn(src[i * 2], src[i * 2 + 1]);
    }
}

// ================= MoE down — f32 weights, BK=32 =================
__global__ __launch_bounds__(256, 2) void moe_down_kernel(const float* __restrict__ Wd)
{
    extern __shared__ char smraw[];
    __half* As = (__half*)smraw;                 // 2 x 128 x 40
    __half* Bs = As + 2 * 128 * A32_LD;          // 2 x 32 x 136
    float*  Cs = (float*)smraw;                  // epilogue 128 x 132 f32
    __shared__ int sPid[128];

    int e = blockIdx.z;
    int count = g_cnt[e];
    int mBase = blockIdx.y * 128;
    if (mBase >= count) return;
    int colBase = blockIdx.x * 128;

    int tx = threadIdx.x;
    if (tx < 128) {
        int r = mBase + tx;
        sPid[tx] = (r < count) ? g_rows[e * T_TOK + r] : -1;
    }
    __syncthreads();

    const float* B = Wd + (size_t)e * INTER * H_DIM;
    int warp = tx >> 5, wm = warp >> 1, wn = warp & 1;

    HFragC c[2][4];
#pragma unroll
    for (int mi = 0; mi < 2; mi++)
#pragma unroll
        for (int ni = 0; ni < 4; ni++) wmma::fill_fragment(c[mi][ni], 0.f);

    int arow = tx >> 1, acol = (tx & 1) * 16;
    int brow = tx >> 3, bcol = (tx & 7) * 16;    // 32 rows x 128 cols, 16 f32/thread
    int pidA = sPid[arow];
    bool valid = (pidA >= 0);
    const __half* aP = g_acth + (valid ? (size_t)pidA * INTER : 0) + acol;
    const float* bP = B + (size_t)brow * H_DIM + colBase + bcol;
    const int nt = INTER >> 5;   // 88

    {
        float4 r0 = *(const float4*)bP;
        float4 r1 = *(const float4*)(bP + 4);
        float4 r2 = *(const float4*)(bP + 8);
        float4 r3 = *(const float4*)(bP + 12);
        cp16(&As[arow * A32_LD + acol],     aP,     valid);
        cp16(&As[arow * A32_LD + acol + 8], aP + 8, valid);
        cp_commit();
        st8h(&Bs[brow * BH_LD + bcol],     r0, r1);
        st8h(&Bs[brow * BH_LD + bcol + 8], r2, r3);
        cp_wait0();
    }
    __syncthreads();

    for (int t = 0; t < nt; t++) {
        int cur = t & 1, nxt = cur ^ 1;
        float4 r0, r1, r2, r3;
        if (t + 1 < nt) {
            const float* b2 = bP + (size_t)(t + 1) * 32 * H_DIM;
            r0 = *(const float4*)b2;
            r1 = *(const float4*)(b2 + 4);
            r2 = *(const float4*)(b2 + 8);
            r3 = *(const float4*)(b2 + 12);
            const __half* a2 = aP + (t + 1) * 32;
            cp16(&As[nxt * 128 * A32_LD + arow * A32_LD + acol],     a2,     valid);
            cp16(&As[nxt * 128 * A32_LD + arow * A32_LD + acol + 8], a2 + 8, valid);
            cp_commit();
        }
#pragma unroll
        for (int kk = 0; kk < 2; kk++) {
            HFragA a[2]; HFragB b[4];
#pragma unroll
            for (int mi = 0; mi < 2; mi++)
                wmma::load_matrix_sync(a[mi], &As[cur * 128 * A32_LD + (wm * 32 + mi * 16) * A32_LD + kk * 16], A32_LD);
#pragma unroll
            for (int ni = 0; ni < 4; ni++)
                wmma::load_matrix_sync(b[ni], &Bs[cur * 32 * BH_LD + (kk * 16) * BH_LD + wn * 64 + ni * 16], BH_LD);
#pragma unroll
            for (int mi = 0; mi < 2; mi++)
#pragma unroll
                for (int ni = 0; ni < 4; ni++)
                    wmma::mma_sync(c[mi][ni], a[mi], b[ni], c[mi][ni]);
        }
        __syncthreads();
        if (t + 1 < nt) {
            st8h(&Bs[nxt * 32 * BH_LD + brow * BH_LD + bcol],     r0, r1);
            st8h(&Bs[nxt * 32 * BH_LD + brow * BH_LD + bcol + 8], r2, r3);
            cp_wait0();
        }
        __syncthreads();
    }

#pragma unroll
    for (int mi = 0; mi < 2; mi++)
#pragma unroll
        for (int ni = 0; ni < 4; ni++)
            wmma::store_matrix_sync(&Cs[(wm * 32 + mi * 16) * CS_LD + wn * 64 + ni * 16],
                                    c[mi][ni], CS_LD, wmma::mem_row_major);
    __syncthreads();

    int orow = tx >> 1, ocol = (tx & 1) * 64;
    int pid = sPid[orow];
    if (pid >= 0) {
        float scale = g_pairw[pid];
        float* dst = g_ypair + (size_t)pid * H_DIM + colBase + ocol;
        const float* src = &Cs[orow * CS_LD + ocol];
#pragma unroll
        for (int i = 0; i < 16; i++) {
            float4 v = *(const float4*)(src + i * 4);
            v.x *= scale; v.y *= scale; v.z *= scale; v.w *= scale;
            *(float4*)(dst + i * 4) = v;
        }
    }
}

// ---------------- block reduce ----------------
__device__ __forceinline__ float blockReduceSum(float v)
{
    __shared__ float red[8];
    int lane = threadIdx.x & 31, warp = threadIdx.x >> 5;
#pragma unroll
    for (int o = 16; o; o >>= 1) v += __shfl_xor_sync(0xffffffffu, v, o);
    if (lane == 0) red[warp] = v;
    __syncthreads();
    if (warp == 0) {
        float t = (lane < 8) ? red[lane] : 0.f;
#pragma unroll
        for (int o = 4; o; o >>= 1) t += __shfl_xor_sync(0xffffffffu, t, o);
        if (lane == 0) red[0] = t;
    }
    __syncthreads();
    return red[0];
}

// ---------------- add + rmsnorm ----------------
__global__ __launch_bounds__(256) void addnorm_kernel(
    const float* __restrict__ a, const float* __restrict__ b)
{
    int t = blockIdx.x, tx = threadIdx.x;
    const float* ap = a + (size_t)t * H_DIM;
    const float* bp = b + (size_t)t * H_DIM;
    float v[4]; float ss = 0.f;
#pragma unroll
    for (int j = 0; j < 4; j++) {
        int i = tx + j * 256;
        float x = ap[i] + bp[i];
        v[j] = x; ss += x * x;
    }
    float tot = blockReduceSum(ss);
    float scale = rsqrtf(tot * (1.f / H_DIM) + 1e-5f);
    float* op = g_hs + (size_t)t * H_DIM;
    __half* oh = g_hsh + (size_t)t * H_DIM;
#pragma unroll
    for (int j = 0; j < 4; j++) {
        int i = tx + j * 256;
        float x = v[j] * scale;
        op[i] = x;
        oh[i] = __float2half_rn(x);
    }
}

// ---------------- routing ----------------
__global__ void zerocnt_kernel() { if (threadIdx.x < NEXP) g_cnt[threadIdx.x] = 0; }

__global__ void route_kernel(const float* __restrict__ wg)
{
    int t = blockIdx.x, lane = threadIdx.x;
    float p[8];
#pragma unroll
    for (int e = 0; e < 8; e++) p[e] = 0.f;
    const float* x = g_hs + (size_t)t * H_DIM;
    for (int h = lane; h < H_DIM; h += 32) {
        float xv = x[h];
#pragma unroll
        for (int e = 0; e < 8; e++) p[e] += xv * wg[h * 8 + e];
    }
#pragma unroll
    for (int e = 0; e < 8; e++)
#pragma unroll
        for (int o = 16; o; o >>= 1) p[e] += __shfl_xor_sync(0xffffffffu, p[e], o);

    if (lane == 0) {
        int e0 = 0; float l0 = p[0];
        for (int e = 1; e < 8; e++) if (p[e] > l0) { l0 = p[e]; e0 = e; }
        int e1 = -1; float l1 = -1e30f;
        for (int e = 0; e < 8; e++) if (e != e0 && p[e] > l1) { l1 = p[e]; e1 = e; }
        float w0 = 1.f / (1.f + expf(l1 - l0));
        float w1 = 1.f - w0;
        int pos0 = atomicAdd(&g_cnt[e0], 1);
        g_rows[e0 * T_TOK + pos0] = t * 2;
        g_pairw[t * 2] = w0;
        int pos1 = atomicAdd(&g_cnt[e1], 1);
        g_rows[e1 * T_TOK + pos1] = t * 2 + 1;
        g_pairw[t * 2 + 1] = w1;
    }
}

// ---------------- final rmsnorm ----------------
__global__ __launch_bounds__(256) void final_kernel(float* __restrict__ out)
{
    int t = blockIdx.x, tx = threadIdx.x;
    const float* hs = g_hs + (size_t)t * H_DIM;
    const float* y0 = g_ypair + (size_t)(t * 2) * H_DIM;
    const float* y1 = y0 + H_DIM;
    float v[4]; float ss = 0.f;
#pragma unroll
    for (int j = 0; j < 4; j++) {
        int i = tx + j * 256;
        float x = hs[i] + y0[i] + y1[i];
        v[j] = x; ss += x * x;
    }
    float tot = blockReduceSum(ss);
    float scale = rsqrtf(tot * (1.f / H_DIM) + 1e-5f);
    float* op = out + (size_t)t * H_DIM;
#pragma unroll
    for (int j = 0; j < 4; j++) op[tx + j * 256] = v[j] * scale;
}

// ---------------- launch ----------------
extern "C" void kernel_launch(void* const* d_in, const int* in_sizes, int n_in,
                              void* d_out, int out_size)
{
    const float* hidden = (const float*)d_in[0];
    const float* cosp   = (const float*)d_in[1];
    const float* sinp   = (const float*)d_in[2];
    const float* w_qkv  = (const float*)d_in[3];
    const float* w_o    = (const float*)d_in[4];
    const float* w_gate = (const float*)d_in[5];
    const float* w_gu   = (const float*)d_in[6];
    const float* w_down = (const float*)d_in[7];
    float* out = (float*)d_out;

    float*  qkv_ptr;  cudaGetSymbolAddress((void**)&qkv_ptr,  g_qkv);
    float*  tmp_ptr;  cudaGetSymbolAddress((void**)&tmp_ptr,  g_tmp);
    __half* hidh_ptr; cudaGetSymbolAddress((void**)&hidh_ptr, g_hidh);
    __half* ctxh_ptr; cudaGetSymbolAddress((void**)&ctxh_ptr, g_ctxh);
    __half* wqkvh_ptr;cudaGetSymbolAddress((void**)&wqkvh_ptr,g_wqkvh);
    __half* woh_ptr;  cudaGetSymbolAddress((void**)&woh_ptr,  g_woh);

    const int GU_SMEM   = (2 * 128 * A32_LD + 4 * 32 * VH_LD) * 2 > 128 * GC_LD * 4
                        ? (2 * 128 * A32_LD + 4 * 32 * VH_LD) * 2 : 128 * GC_LD * 4;   // max(38.9, 34.8) KB
    const int DOWN_SMEM = (2 * 128 * A32_LD + 2 * 32 * BH_LD) * 2 > 128 * CS_LD * 4
                        ? (2 * 128 * A32_LD + 2 * 32 * BH_LD) * 2 : 128 * CS_LD * 4;   // max(37.9, 67.6) KB
    const int ATT_SMEM  = 144384;
    static bool attrs_set = false;
    if (!attrs_set) {
        cudaFuncSetAttribute(moe_gateup_kernel, cudaFuncAttributeMaxDynamicSharedMemorySize, GU_SMEM);
        cudaFuncSetAttribute(moe_down_kernel,   cudaFuncAttributeMaxDynamicSharedMemorySize, DOWN_SMEM);
        cudaFuncSetAttribute(attn_fused_kernel, cudaFuncAttributeMaxDynamicSharedMemorySize, ATT_SMEM);
        attrs_set = true;
    }

    auto cvt = [](const float* in, __half* out, size_t n) {
        cvt_kernel<<<(unsigned)((n / 4 + 255) / 256), 256>>>(in, out, n);
    };

    // 0. f32 -> f16 conversions (small tensors only)
    cvt(hidden, hidh_ptr,  (size_t)T_TOK * H_DIM);
    cvt(w_qkv,  wqkvh_ptr, (size_t)H_DIM * 3 * H_DIM);
    cvt(w_o,    woh_ptr,   (size_t)H_DIM * H_DIM);

    // 1. QKV projection (BK=32)
    gemm_f16_kernel<<<dim3(3072 / 128, 2048 / 128), 256>>>(hidh_ptr, wqkvh_ptr, qkv_ptr, 2048, 3072, 1024);

    // 2. RoPE -> f16 qkv
    rope_kernel<<<(T_TOK * NHEAD * 32) / 256, 256>>>(cosp, sinp);

    // 3. fused flash attention -> g_ctxh
    attn_fused_kernel<<<dim3(8, 32), 256, ATT_SMEM>>>();

    // 4. O projection (BK=32)
    gemm_f16_kernel<<<dim3(1024 / 128, 2048 / 128), 256>>>(ctxh_ptr, woh_ptr, tmp_ptr, 2048, 1024, 1024);

    // 5. hs = rmsnorm(x + attn_out)
    addnorm_kernel<<<T_TOK, 256>>>(hidden, tmp_ptr);

    // 6. routing
    zerocnt_kernel<<<1, 32>>>();
    route_kernel<<<T_TOK, 32>>>(w_gate);

    // 7. fused gate_up + silu -> g_acth (f32 weights, BK=32)
    moe_gateup_kernel<<<dim3(INTER / 64, 2048 / 128, NEXP), 256, GU_SMEM>>>(w_gu);

    // 8. down proj (weighted) -> g_ypair (f32 weights, BK=32)
    moe_down_kernel<<<dim3(1024 / 128, 2048 / 128, NEXP), 256, DOWN_SMEM>>>(w_down);

    // 9. out = rmsnorm(hs + mixed)
    final_kernel<<<T_TOK, 256>>>(out);
}

// round 17
// speedup vs baseline: 1.1146x; 1.0894x over previous
#include <cuda_runtime.h>
#include <mma.h>
#include <cuda_fp16.h>
#include <math.h>
#include <cstdint>

using namespace nvcuda;

// ---------------- problem constants ----------------
#define T_TOK 2048
#define S_LEN 1024
#define H_DIM 1024
#define NHEAD 16
#define HD    64
#define NEXP  8
#define INTER 2816
#define GU2   (2*INTER)

// ---------------- device scratch ----------------
__device__ float  g_qkv [(size_t)T_TOK * 3 * H_DIM];
__device__ __half g_qkvh[(size_t)T_TOK * 3 * H_DIM];
__device__ __half g_ctxh[(size_t)T_TOK * H_DIM];
__device__ float  g_tmp [(size_t)T_TOK * H_DIM];
__device__ float  g_hs  [(size_t)T_TOK * H_DIM];
__device__ __half g_hsh [(size_t)T_TOK * H_DIM];
__device__ __half g_acth[(size_t)T_TOK * 2 * INTER];
__device__ float  g_ypair[(size_t)T_TOK * 2 * H_DIM];
__device__ __half g_hidh[(size_t)T_TOK * H_DIM];
__device__ __half g_wqkvh[(size_t)H_DIM * 3 * H_DIM];
__device__ __half g_woh [(size_t)H_DIM * H_DIM];
__device__ float  g_pairw[T_TOK * 2];
__device__ int    g_cnt [NEXP];
__device__ int    g_rows[NEXP * T_TOK];

// ---------------- cp.async helpers ----------------
__device__ __forceinline__ void cp16(void* s, const void* g, bool pred) {
    unsigned int sa = (unsigned int)__cvta_generic_to_shared(s);
    int sz = pred ? 16 : 0;
    asm volatile("cp.async.cg.shared.global [%0], [%1], 16, %2;\n" :: "r"(sa), "l"(g), "r"(sz));
}
__device__ __forceinline__ void cp_commit() { asm volatile("cp.async.commit_group;\n"); }
__device__ __forceinline__ void cp_wait1()  { asm volatile("cp.async.wait_group 1;\n" ::: "memory"); }
__device__ __forceinline__ void cp_wait0()  { asm volatile("cp.async.wait_group 0;\n" ::: "memory"); }

// pack 8 f32 -> 8 f16 and store as uint4
__device__ __forceinline__ void st8h(__half* dst, float4 r0, float4 r1) {
    __half2 h0 = __floats2half2_rn(r0.x, r0.y);
    __half2 h1 = __floats2half2_rn(r0.z, r0.w);
    __half2 h2 = __floats2half2_rn(r1.x, r1.y);
    __half2 h3 = __floats2half2_rn(r1.z, r1.w);
    uint4 pk;
    pk.x = *reinterpret_cast<unsigned*>(&h0);
    pk.y = *reinterpret_cast<unsigned*>(&h1);
    pk.z = *reinterpret_cast<unsigned*>(&h2);
    pk.w = *reinterpret_cast<unsigned*>(&h3);
    *reinterpret_cast<uint4*>(dst) = pk;
}

// shared layouts (elements)
#define A32_LD 40    // A stage: 128 x 32 halves (+pad)
#define BH_LD 136    // B stage: 32 x 128 halves (+pad)
#define VH_LD 72     // gate/up B stage: 32 x 64 halves (+pad)
// f32 epilogue stages
#define CS_LD 132
#define GC_LD 68
// fused attention layouts
#define FA_QLD 72
#define FA_SLD 68

typedef wmma::fragment<wmma::matrix_a, 16, 16, 16, __half, wmma::row_major> HFragA;
typedef wmma::fragment<wmma::matrix_b, 16, 16, 16, __half, wmma::row_major> HFragB;
typedef wmma::fragment<wmma::matrix_b, 16, 16, 16, __half, wmma::col_major> HFragBc;
typedef wmma::fragment<wmma::accumulator, 16, 16, 16, float> HFragC;

// ---------------- f32 -> f16 conversion ----------------
__global__ void cvt_kernel(const float* __restrict__ in, __half* __restrict__ out, size_t n)
{
    size_t i = ((size_t)blockIdx.x * blockDim.x + threadIdx.x) * 4;
    if (i >= n) return;
    float4 v = *(const float4*)(in + i);
    *(__half2*)(out + i)     = __floats2half2_rn(v.x, v.y);
    *(__half2*)(out + i + 2) = __floats2half2_rn(v.z, v.w);
}

// ================= plain FP16 GEMM: BK=32, 3-stage, 1 barrier/slab =================
__global__ __launch_bounds__(256, 2) void gemm_f16_kernel(
    const __half* __restrict__ A, const __half* __restrict__ B,
    float* __restrict__ C, int M, int N, int K)
{
    extern __shared__ char smraw[];
    __half* As = (__half*)smraw;                       // 3 x 128 x 40
    __half* Bs = As + 3 * 128 * A32_LD;                // 3 x 32 x 136

    int tx = threadIdx.x;
    int rowBase = blockIdx.y * 128;
    int colBase = blockIdx.x * 128;
    int warp = tx >> 5, wm = warp >> 1, wn = warp & 1;

    HFragC c[2][4];
#pragma unroll
    for (int mi = 0; mi < 2; mi++)
#pragma unroll
        for (int ni = 0; ni < 4; ni++) wmma::fill_fragment(c[mi][ni], 0.f);

    int arow = tx >> 1, acol = (tx & 1) * 16;
    int brow = tx >> 3, bcol = (tx & 7) * 16;
    const __half* aP = A + (size_t)(rowBase + arow) * K + acol;
    const __half* bP = B + (size_t)brow * N + colBase + bcol;
    int nt = K >> 5;

#pragma unroll
    for (int s = 0; s < 2; s++) {
        const __half* a2 = aP + s * 32;
        const __half* b2 = bP + (size_t)s * 32 * N;
        cp16(&As[s * 128 * A32_LD + arow * A32_LD + acol],     a2,     true);
        cp16(&As[s * 128 * A32_LD + arow * A32_LD + acol + 8], a2 + 8, true);
        cp16(&Bs[s * 32 * BH_LD + brow * BH_LD + bcol],        b2,     true);
        cp16(&Bs[s * 32 * BH_LD + brow * BH_LD + bcol + 8],    b2 + 8, true);
        cp_commit();
    }

    int sc = 0, sp = 2;   // compute stage, prefetch stage
    for (int t = 0; t < nt; t++) {
        if (t + 1 < nt) cp_wait1(); else cp_wait0();
        __syncthreads();
        if (t + 2 < nt) {
            const __half* a2 = aP + (t + 2) * 32;
            const __half* b2 = bP + (size_t)(t + 2) * 32 * N;
            cp16(&As[sp * 128 * A32_LD + arow * A32_LD + acol],     a2,     true);
            cp16(&As[sp * 128 * A32_LD + arow * A32_LD + acol + 8], a2 + 8, true);
            cp16(&Bs[sp * 32 * BH_LD + brow * BH_LD + bcol],        b2,     true);
            cp16(&Bs[sp * 32 * BH_LD + brow * BH_LD + bcol + 8],    b2 + 8, true);
            cp_commit();
        }
        const __half* Ac = &As[sc * 128 * A32_LD];
        const __half* Bc = &Bs[sc * 32 * BH_LD];
#pragma unroll
        for (int kk = 0; kk < 2; kk++) {
            HFragA a[2]; HFragB b[4];
#pragma unroll
            for (int mi = 0; mi < 2; mi++)
                wmma::load_matrix_sync(a[mi], &Ac[(wm * 32 + mi * 16) * A32_LD + kk * 16], A32_LD);
#pragma unroll
            for (int ni = 0; ni < 4; ni++)
                wmma::load_matrix_sync(b[ni], &Bc[(kk * 16) * BH_LD + wn * 64 + ni * 16], BH_LD);
#pragma unroll
            for (int mi = 0; mi < 2; mi++)
#pragma unroll
                for (int ni = 0; ni < 4; ni++)
                    wmma::mma_sync(c[mi][ni], a[mi], b[ni], c[mi][ni]);
        }
        sc = (sc == 2) ? 0 : sc + 1;
        sp = (sp == 2) ? 0 : sp + 1;
    }
#pragma unroll
    for (int mi = 0; mi < 2; mi++)
#pragma unroll
        for (int ni = 0; ni < 4; ni++)
            wmma::store_matrix_sync(
                &C[(size_t)(rowBase + wm * 32 + mi * 16) * N + colBase + wn * 64 + ni * 16],
                c[mi][ni], N, wmma::mem_row_major);
}

// ================= RoPE: f32 g_qkv -> f16 g_qkvh =================
__global__ void rope_kernel(const float* __restrict__ cosp, const float* __restrict__ sinp)
{
    int idx = blockIdx.x * blockDim.x + threadIdx.x;
    if (idx >= T_TOK * NHEAD * 32) return;
    int d = idx & 31;
    int n = (idx >> 5) & 15;
    int t = idx >> 9;
    int s = t & (S_LEN - 1);
    float c1 = cosp[s * 64 + d],      s1 = sinp[s * 64 + d];
    float c2 = cosp[s * 64 + d + 32], s2 = sinp[s * 64 + d + 32];
    size_t base = (size_t)t * 3072 + n * 64 + d;
    float x1 = g_qkv[base], x2 = g_qkv[base + 32];
    g_qkvh[base]      = __float2half_rn(x1 * c1 - x2 * s1);
    g_qkvh[base + 32] = __float2half_rn(x2 * c2 + x1 * s2);
    x1 = g_qkv[base + 1024]; x2 = g_qkv[base + 1056];
    g_qkvh[base + 1024] = __float2half_rn(x1 * c1 - x2 * s1);
    g_qkvh[base + 1056] = __float2half_rn(x2 * c2 + x1 * s2);
    g_qkvh[base + 2048] = __float2half_rn(g_qkv[base + 2048]);
    g_qkvh[base + 2080] = __float2half_rn(g_qkv[base + 2080]);
}

// ================= FUSED flash attention (unchanged) =================
__global__ __launch_bounds__(256) void attn_fused_kernel()
{
    extern __shared__ char smraw[];
    __half* Qs = (__half*)smraw;
    __half* Ks = (__half*)(smraw + 18432);
    __half* Vs = (__half*)(smraw + 36864);
    __half* Ps = (__half*)(smraw + 55296);
    float*  Ss = (float*)(smraw + 73728);
    float*  Os = (float*)(smraw + 108544);
    float*  mrow = (float*)(smraw + 143360);
    float*  lrow = (float*)(smraw + 143872);

    int z = blockIdx.y;
    int b = z >> 4, h = z & 15;
    int qBase = blockIdx.x * 128;
    int tbase = b * S_LEN;
    int tx = threadIdx.x;
    int warp = tx >> 5, wm = warp >> 1, wn = warp & 1;

    {
        int r = tx >> 1, cs = (tx & 1) * 32;
        const __half* qp = g_qkvh + (size_t)(tbase + qBase + r) * 3072 + h * 64 + cs;
#pragma unroll
        for (int j = 0; j < 4; j++) cp16(&Qs[r * FA_QLD + cs + j * 8], qp + j * 8, true);
        int kr = tx >> 2, kcs = (tx & 3) * 16;
        const __half* kp = g_qkvh + (size_t)(tbase + kr) * 3072 + 1024 + h * 64 + kcs;
        cp16(&Ks[kr * FA_QLD + kcs], kp, true);
        cp16(&Ks[kr * FA_QLD + kcs + 8], kp + 8, true);
        cp16(&Vs[kr * FA_QLD + kcs], kp + 1024, true);
        cp16(&Vs[kr * FA_QLD + kcs + 8], kp + 1024 + 8, true);
        cp_commit();
    }
#pragma unroll
    for (int j = 0; j < 34; j++) Os[tx + j * 256] = 0.f;
    if (tx < 128) { mrow[tx] = -1e30f; lrow[tx] = 0.f; }
    cp_wait0();
    __syncthreads();

    const int row2 = tx >> 1, half2 = tx & 1;

    for (int t = 0; t < 16; t++) {
        int cur = t & 1, nxt = cur ^ 1;
        if (t + 1 < 16) {
            int kr = tx >> 2, kcs = (tx & 3) * 16;
            const __half* kp = g_qkvh + (size_t)(tbase + (t + 1) * 64 + kr) * 3072 + 1024 + h * 64 + kcs;
            cp16(&Ks[nxt * 64 * FA_QLD + kr * FA_QLD + kcs], kp, true);
            cp16(&Ks[nxt * 64 * FA_QLD + kr * FA_QLD + kcs + 8], kp + 8, true);
            cp16(&Vs[nxt * 64 * FA_QLD + kr * FA_QLD + kcs], kp + 1024, true);
            cp16(&Vs[nxt * 64 * FA_QLD + kr * FA_QLD + kcs + 8], kp + 1024 + 8, true);
            cp_commit();
        }

        {
            HFragC cs[2][2];
#pragma unroll
            for (int mi = 0; mi < 2; mi++)
#pragma unroll
                for (int ni = 0; ni < 2; ni++) wmma::fill_fragment(cs[mi][ni], 0.f);
#pragma unroll
            for (int kk = 0; kk < 4; kk++) {
                HFragA a[2]; HFragBc bb[2];
#pragma unroll
                for (int mi = 0; mi < 2; mi++)
                    wmma::load_matrix_sync(a[mi], &Qs[(wm * 32 + mi * 16) * FA_QLD + kk * 16], FA_QLD);
#pragma unroll
                for (int ni = 0; ni < 2; ni++)
                    wmma::load_matrix_sync(bb[ni], &Ks[cur * 64 * FA_QLD + (wn * 32 + ni * 16) * FA_QLD + kk * 16], FA_QLD);
#pragma unroll
                for (int mi = 0; mi < 2; mi++)
#pragma unroll
                    for (int ni = 0; ni < 2; ni++)
                        wmma::mma_sync(cs[mi][ni], a[mi], bb[ni], cs[mi][ni]);
            }
#pragma unroll
            for (int mi = 0; mi < 2; mi++)
#pragma unroll
                for (int ni = 0; ni < 2; ni++) {
#pragma unroll
                    for (int i = 0; i < cs[mi][ni].num_elements; i++) cs[mi][ni].x[i] *= 0.125f;
                    wmma::store_matrix_sync(&Ss[(wm * 32 + mi * 16) * FA_SLD + wn * 32 + ni * 16],
                                            cs[mi][ni], FA_SLD, wmma::mem_row_major);
                }
        }
        __syncthreads();

        {
            const float* srow = &Ss[row2 * FA_SLD + half2 * 32];
            float s[32];
            float tmax = -1e30f;
#pragma unroll
            for (int i = 0; i < 32; i++) { s[i] = srow[i]; tmax = fmaxf(tmax, s[i]); }
            tmax = fmaxf(tmax, __shfl_xor_sync(0xffffffffu, tmax, 1));
            float m_old = mrow[row2];
            float m_new = fmaxf(m_old, tmax);
            float alpha = __expf(m_old - m_new);
            float psum = 0.f;
            __half* prow = &Ps[row2 * FA_QLD + half2 * 32];
#pragma unroll
            for (int i = 0; i < 32; i += 2) {
                float p0 = __expf(s[i] - m_new);
                float p1 = __expf(s[i + 1] - m_new);
                psum += p0 + p1;
                *(__half2*)(prow + i) = __floats2half2_rn(p0, p1);
            }
            psum += __shfl_xor_sync(0xffffffffu, psum, 1);
            if (half2 == 0) {
                mrow[row2] = m_new;
                lrow[row2] = lrow[row2] * alpha + psum;
            }
            float* orow = &Os[row2 * FA_SLD + half2 * 32];
#pragma unroll
            for (int i = 0; i < 32; i++) orow[i] *= alpha;
        }
        __syncthreads();

        {
            HFragC co[2][2];
#pragma unroll
            for (int mi = 0; mi < 2; mi++)
#pragma unroll
                for (int ni = 0; ni < 2; ni++)
                    wmma::load_matrix_sync(co[mi][ni], &Os[(wm * 32 + mi * 16) * FA_SLD + wn * 32 + ni * 16],
                                           FA_SLD, wmma::mem_row_major);
#pragma unroll
            for (int kk = 0; kk < 4; kk++) {
                HFragA a[2]; HFragB bb[2];
#pragma unroll
                for (int mi = 0; mi < 2; mi++)
                    wmma::load_matrix_sync(a[mi], &Ps[(wm * 32 + mi * 16) * FA_QLD + kk * 16], FA_QLD);
#pragma unroll
                for (int ni = 0; ni < 2; ni++)
                    wmma::load_matrix_sync(bb[ni], &Vs[cur * 64 * FA_QLD + (kk * 16) * FA_QLD + wn * 32 + ni * 16], FA_QLD);
#pragma unroll
                for (int mi = 0; mi < 2; mi++)
#pragma unroll
                    for (int ni = 0; ni < 2; ni++)
                        wmma::mma_sync(co[mi][ni], a[mi], bb[ni], co[mi][ni]);
            }
#pragma unroll
            for (int mi = 0; mi < 2; mi++)
#pragma unroll
                for (int ni = 0; ni < 2; ni++)
                    wmma::store_matrix_sync(&Os[(wm * 32 + mi * 16) * FA_SLD + wn * 32 + ni * 16],
                                            co[mi][ni], FA_SLD, wmma::mem_row_major);
        }
        if (t + 1 < 16) cp_wait0();
        __syncthreads();
    }

    {
        float inv = 1.f / lrow[row2];
        const float* orow = &Os[row2 * FA_SLD + half2 * 32];
        __half* dst = g_ctxh + (size_t)(tbase + qBase + row2) * H_DIM + h * 64 + half2 * 32;
#pragma unroll
        for (int i = 0; i < 32; i += 2)
            *(__half2*)(dst + i) = __floats2half2_rn(orow[i] * inv, orow[i + 1] * inv);
    }
}

// ================= MoE gate_up fused silu — f32 weights, BK=32, 3-stage, 1 barrier ======
__global__ __launch_bounds__(256, 2) void moe_gateup_kernel(const float* __restrict__ Wgu)
{
    extern __shared__ char smraw[];
    __half* As = (__half*)smraw;                 // 3 x 128 x 40 halves (30.7 KB)
    __half* Bg = As + 3 * 128 * A32_LD;          // 3 x 32 x 72
    __half* Bu = Bg + 3 * 32 * VH_LD;            // 3 x 32 x 72
    float*  Cs = (float*)smraw;                  // epilogue: 128 x 68 f32 (34.8 KB)
    __shared__ int sPid[128];

    int e = blockIdx.z;
    int count = g_cnt[e];
    int mBase = blockIdx.y * 128;
    if (mBase >= count) return;
    int nBase = blockIdx.x * 64;

    int tx = threadIdx.x;
    if (tx < 128) {
        int r = mBase + tx;
        sPid[tx] = (r < count) ? g_rows[e * T_TOK + r] : -1;
    }
    __syncthreads();

    const float* B = Wgu + (size_t)e * H_DIM * GU2;
    int warp = tx >> 5, wm = warp >> 1, wn = warp & 1;

    HFragC cg[2][2], cu[2][2];
#pragma unroll
    for (int mi = 0; mi < 2; mi++)
#pragma unroll
        for (int ni = 0; ni < 2; ni++) { wmma::fill_fragment(cg[mi][ni], 0.f); wmma::fill_fragment(cu[mi][ni], 0.f); }

    int arow = tx >> 1, acol = (tx & 1) * 16;
    int pidA = sPid[arow];
    bool valid = (pidA >= 0);
    const __half* aP = g_hsh + (valid ? (size_t)(pidA >> 1) * H_DIM : 0) + acol;
    int btx = tx & 127;
    int brow = btx >> 2, bcol = (btx & 3) * 16;   // 32 rows x 64 cols, 16 f32/thread
    bool isUp = (tx >= 128);
    const float* bP = B + (size_t)brow * GU2 + nBase + bcol + (isUp ? INTER : 0);
    __half* Bdst = isUp ? Bu : Bg;
    const int nt = H_DIM >> 5;   // 32

    // prologue: B0,B1 staged; A0,A1 committed
#pragma unroll
    for (int s = 0; s < 2; s++) {
        const float* b2 = bP + (size_t)s * 32 * GU2;
        float4 r0 = *(const float4*)b2;
        float4 r1 = *(const float4*)(b2 + 4);
        float4 r2 = *(const float4*)(b2 + 8);
        float4 r3 = *(const float4*)(b2 + 12);
        st8h(&Bdst[s * 32 * VH_LD + brow * VH_LD + bcol],     r0, r1);
        st8h(&Bdst[s * 32 * VH_LD + brow * VH_LD + bcol + 8], r2, r3);
        const __half* a2 = aP + s * 32;
        cp16(&As[s * 128 * A32_LD + arow * A32_LD + acol],     a2,     valid);
        cp16(&As[s * 128 * A32_LD + arow * A32_LD + acol + 8], a2 + 8, valid);
        cp_commit();
    }

    int sc = 0, sp = 2;
    for (int t = 0; t < nt; t++) {
        float4 r0, r1, r2, r3;
        if (t + 2 < nt) {
            const float* b2 = bP + (size_t)(t + 2) * 32 * GU2;
            r0 = *(const float4*)b2;
            r1 = *(const float4*)(b2 + 4);
            r2 = *(const float4*)(b2 + 8);
            r3 = *(const float4*)(b2 + 12);
        }
        if (t + 1 < nt) cp_wait1(); else cp_wait0();
        __syncthreads();
        if (t + 2 < nt) {
            st8h(&Bdst[sp * 32 * VH_LD + brow * VH_LD + bcol],     r0, r1);
            st8h(&Bdst[sp * 32 * VH_LD + brow * VH_LD + bcol + 8], r2, r3);
            const __half* a2 = aP + (t + 2) * 32;
            cp16(&As[sp * 128 * A32_LD + arow * A32_LD + acol],     a2,     valid);
            cp16(&As[sp * 128 * A32_LD + arow * A32_LD + acol + 8], a2 + 8, valid);
            cp_commit();
        }
        const __half* Ac = &As[sc * 128 * A32_LD];
        const __half* Bgc = &Bg[sc * 32 * VH_LD];
        const __half* Buc = &Bu[sc * 32 * VH_LD];
#pragma unroll
        for (int kk = 0; kk < 2; kk++) {
            HFragA a[2];
#pragma unroll
            for (int mi = 0; mi < 2; mi++)
                wmma::load_matrix_sync(a[mi], &Ac[(wm * 32 + mi * 16) * A32_LD + kk * 16], A32_LD);
#pragma unroll
            for (int ni = 0; ni < 2; ni++) {
                HFragB bg;
                wmma::load_matrix_sync(bg, &Bgc[(kk * 16) * VH_LD + wn * 32 + ni * 16], VH_LD);
#pragma unroll
                for (int mi = 0; mi < 2; mi++)
                    wmma::mma_sync(cg[mi][ni], a[mi], bg, cg[mi][ni]);
                HFragB bu;
                wmma::load_matrix_sync(bu, &Buc[(kk * 16) * VH_LD + wn * 32 + ni * 16], VH_LD);
#pragma unroll
                for (int mi = 0; mi < 2; mi++)
                    wmma::mma_sync(cu[mi][ni], a[mi], bu, cu[mi][ni]);
            }
        }
        sc = (sc == 2) ? 0 : sc + 1;
        sp = (sp == 2) ? 0 : sp + 1;
    }
    __syncthreads();   // protect epilogue smem reuse

#pragma unroll
    for (int mi = 0; mi < 2; mi++)
#pragma unroll
        for (int ni = 0; ni < 2; ni++) {
#pragma unroll
            for (int i = 0; i < cg[mi][ni].num_elements; i++) {
                float g = cg[mi][ni].x[i];
                cg[mi][ni].x[i] = g / (1.f + __expf(-g)) * cu[mi][ni].x[i];
            }
            wmma::store_matrix_sync(&Cs[(wm * 32 + mi * 16) * GC_LD + wn * 32 + ni * 16],
                                    cg[mi][ni], GC_LD, wmma::mem_row_major);
        }
    __syncthreads();

    int orow = tx >> 1, ocol = (tx & 1) * 32;
    int pid = sPid[orow];
    if (pid >= 0) {
        __half* dst = g_acth + (size_t)pid * INTER + nBase + ocol;
        const float* src = &Cs[orow * GC_LD + ocol];
#pragma unroll
        for (int i = 0; i < 16; i++)
            *(__half2*)(dst + i * 2) = __floats2half2_rn(src[i * 2], src[i * 2 + 1]);
    }
}

// ================= MoE down — f32 weights, BK=32, 3-stage, 1 barrier =================
__global__ __launch_bounds__(256, 2) void moe_down_kernel(const float* __restrict__ Wd)
{
    extern __shared__ char smraw[];
    __half* As = (__half*)smraw;                 // 3 x 128 x 40
    __half* Bs = As + 3 * 128 * A32_LD;          // 3 x 32 x 136
    float*  Cs = (float*)smraw;                  // epilogue 128 x 132 f32
    __shared__ int sPid[128];

    int e = blockIdx.z;
    int count = g_cnt[e];
    int mBase = blockIdx.y * 128;
    if (mBase >= count) return;
    int colBase = blockIdx.x * 128;

    int tx = threadIdx.x;
    if (tx < 128) {
        int r = mBase + tx;
        sPid[tx] = (r < count) ? g_rows[e * T_TOK + r] : -1;
    }
    __syncthreads();

    const float* B = Wd + (size_t)e * INTER * H_DIM;
    int warp = tx >> 5, wm = warp >> 1, wn = warp & 1;

    HFragC c[2][4];
#pragma unroll
    for (int mi = 0; mi < 2; mi++)
#pragma unroll
        for (int ni = 0; ni < 4; ni++) wmma::fill_fragment(c[mi][ni], 0.f);

    int arow = tx >> 1, acol = (tx & 1) * 16;
    int brow = tx >> 3, bcol = (tx & 7) * 16;
    int pidA = sPid[arow];
    bool valid = (pidA >= 0);
    const __half* aP = g_acth + (valid ? (size_t)pidA * INTER : 0) + acol;
    const float* bP = B + (size_t)brow * H_DIM + colBase + bcol;
    const int nt = INTER >> 5;   // 88

#pragma unroll
    for (int s = 0; s < 2; s++) {
        const float* b2 = bP + (size_t)s * 32 * H_DIM;
        float4 r0 = *(const float4*)b2;
        float4 r1 = *(const float4*)(b2 + 4);
        float4 r2 = *(const float4*)(b2 + 8);
        float4 r3 = *(const float4*)(b2 + 12);
        st8h(&Bs[s * 32 * BH_LD + brow * BH_LD + bcol],     r0, r1);
        st8h(&Bs[s * 32 * BH_LD + brow * BH_LD + bcol + 8], r2, r3);
        const __half* a2 = aP + s * 32;
        cp16(&As[s * 128 * A32_LD + arow * A32_LD + acol],     a2,     valid);
        cp16(&As[s * 128 * A32_LD + arow * A32_LD + acol + 8], a2 + 8, valid);
        cp_commit();
    }

    int sc = 0, sp = 2;
    for (int t = 0; t < nt; t++) {
        float4 r0, r1, r2, r3;
        if (t + 2 < nt) {
            const float* b2 = bP + (size_t)(t + 2) * 32 * H_DIM;
            r0 = *(const float4*)b2;
            r1 = *(const float4*)(b2 + 4);
            r2 = *(const float4*)(b2 + 8);
            r3 = *(const float4*)(b2 + 12);
        }
        if (t + 1 < nt) cp_wait1(); else cp_wait0();
        __syncthreads();
        if (t + 2 < nt) {
            st8h(&Bs[sp * 32 * BH_LD + brow * BH_LD + bcol],     r0, r1);
            st8h(&Bs[sp * 32 * BH_LD + brow * BH_LD + bcol + 8], r2, r3);
            const __half* a2 = aP + (t + 2) * 32;
            cp16(&As[sp * 128 * A32_LD + arow * A32_LD + acol],     a2,     valid);
            cp16(&As[sp * 128 * A32_LD + arow * A32_LD + acol + 8], a2 + 8, valid);
            cp_commit();
        }
        const __half* Ac = &As[sc * 128 * A32_LD];
        const __half* Bc = &Bs[sc * 32 * BH_LD];
#pragma unroll
        for (int kk = 0; kk < 2; kk++) {
            HFragA a[2]; HFragB b[4];
#pragma unroll
            for (int mi = 0; mi < 2; mi++)
                wmma::load_matrix_sync(a[mi], &Ac[(wm * 32 + mi * 16) * A32_LD + kk * 16], A32_LD);
#pragma unroll
            for (int ni = 0; ni < 4; ni++)
                wmma::load_matrix_sync(b[ni], &Bc[(kk * 16) * BH_LD + wn * 64 + ni * 16], BH_LD);
#pragma unroll
            for (int mi = 0; mi < 2; mi++)
#pragma unroll
                for (int ni = 0; ni < 4; ni++)
                    wmma::mma_sync(c[mi][ni], a[mi], b[ni], c[mi][ni]);
        }
        sc = (sc == 2) ? 0 : sc + 1;
        sp = (sp == 2) ? 0 : sp + 1;
    }
    __syncthreads();

#pragma unroll
    for (int mi = 0; mi < 2; mi++)
#pragma unroll
        for (int ni = 0; ni < 4; ni++)
            wmma::store_matrix_sync(&Cs[(wm * 32 + mi * 16) * CS_LD + wn * 64 + ni * 16],
                                    c[mi][ni], CS_LD, wmma::mem_row_major);
    __syncthreads();

    int orow = tx >> 1, ocol = (tx & 1) * 64;
    int pid = sPid[orow];
    if (pid >= 0) {
        float scale = g_pairw[pid];
        float* dst = g_ypair + (size_t)pid * H_DIM + colBase + ocol;
        const float* src = &Cs[orow * CS_LD + ocol];
#pragma unroll
        for (int i = 0; i < 16; i++) {
            float4 v = *(const float4*)(src + i * 4);
            v.x *= scale; v.y *= scale; v.z *= scale; v.w *= scale;
            *(float4*)(dst + i * 4) = v;
        }
    }
}

// ---------------- block reduce ----------------
__device__ __forceinline__ float blockReduceSum(float v)
{
    __shared__ float red[8];
    int lane = threadIdx.x & 31, warp = threadIdx.x >> 5;
#pragma unroll
    for (int o = 16; o; o >>= 1) v += __shfl_xor_sync(0xffffffffu, v, o);
    if (lane == 0) red[warp] = v;
    __syncthreads();
    if (warp == 0) {
        float t = (lane < 8) ? red[lane] : 0.f;
#pragma unroll
        for (int o = 4; o; o >>= 1) t += __shfl_xor_sync(0xffffffffu, t, o);
        if (lane == 0) red[0] = t;
    }
    __syncthreads();
    return red[0];
}

// ---------------- add + rmsnorm ----------------
__global__ __launch_bounds__(256) void addnorm_kernel(
    const float* __restrict__ a, const float* __restrict__ b)
{
    int t = blockIdx.x, tx = threadIdx.x;
    const float* ap = a + (size_t)t * H_DIM;
    const float* bp = b + (size_t)t * H_DIM;
    float v[4]; float ss = 0.f;
#pragma unroll
    for (int j = 0; j < 4; j++) {
        int i = tx + j * 256;
        float x = ap[i] + bp[i];
        v[j] = x; ss += x * x;
    }
    float tot = blockReduceSum(ss);
    float scale = rsqrtf(tot * (1.f / H_DIM) + 1e-5f);
    float* op = g_hs + (size_t)t * H_DIM;
    __half* oh = g_hsh + (size_t)t * H_DIM;
#pragma unroll
    for (int j = 0; j < 4; j++) {
        int i = tx + j * 256;
        float x = v[j] * scale;
        op[i] = x;
        oh[i] = __float2half_rn(x);
    }
}

// ---------------- routing ----------------
__global__ void zerocnt_kernel() { if (threadIdx.x < NEXP) g_cnt[threadIdx.x] = 0; }

__global__ void route_kernel(const float* __restrict__ wg)
{
    int t = blockIdx.x, lane = threadIdx.x;
    float p[8];
#pragma unroll
    for (int e = 0; e < 8; e++) p[e] = 0.f;
    const float* x = g_hs + (size_t)t * H_DIM;
    for (int h = lane; h < H_DIM; h += 32) {
        float xv = x[h];
#pragma unroll
        for (int e = 0; e < 8; e++) p[e] += xv * wg[h * 8 + e];
    }
#pragma unroll
    for (int e = 0; e < 8; e++)
#pragma unroll
        for (int o = 16; o; o >>= 1) p[e] += __shfl_xor_sync(0xffffffffu, p[e], o);

    if (lane == 0) {
        int e0 = 0; float l0 = p[0];
        for (int e = 1; e < 8; e++) if (p[e] > l0) { l0 = p[e]; e0 = e; }
        int e1 = -1; float l1 = -1e30f;
        for (int e = 0; e < 8; e++) if (e != e0 && p[e] > l1) { l1 = p[e]; e1 = e; }
        float w0 = 1.f / (1.f + expf(l1 - l0));
        float w1 = 1.f - w0;
        int pos0 = atomicAdd(&g_cnt[e0], 1);
        g_rows[e0 * T_TOK + pos0] = t * 2;
        g_pairw[t * 2] = w0;
        int pos1 = atomicAdd(&g_cnt[e1], 1);
        g_rows[e1 * T_TOK + pos1] = t * 2 + 1;
        g_pairw[t * 2 + 1] = w1;
    }
}

// ---------------- final rmsnorm ----------------
__global__ __launch_bounds__(256) void final_kernel(float* __restrict__ out)
{
    int t = blockIdx.x, tx = threadIdx.x;
    const float* hs = g_hs + (size_t)t * H_DIM;
    const float* y0 = g_ypair + (size_t)(t * 2) * H_DIM;
    const float* y1 = y0 + H_DIM;
    float v[4]; float ss = 0.f;
#pragma unroll
    for (int j = 0; j < 4; j++) {
        int i = tx + j * 256;
        float x = hs[i] + y0[i] + y1[i];
        v[j] = x; ss += x * x;
    }
    float tot = blockReduceSum(ss);
    float scale = rsqrtf(tot * (1.f / H_DIM) + 1e-5f);
    float* op = out + (size_t)t * H_DIM;
#pragma unroll
    for (int j = 0; j < 4; j++) op[tx + j * 256] = v[j] * scale;
}

// ---------------- launch ----------------
extern "C" void kernel_launch(void* const* d_in, const int* in_sizes, int n_in,
                              void* d_out, int out_size)
{
    const float* hidden = (const float*)d_in[0];
    const float* cosp   = (const float*)d_in[1];
    const float* sinp   = (const float*)d_in[2];
    const float* w_qkv  = (const float*)d_in[3];
    const float* w_o    = (const float*)d_in[4];
    const float* w_gate = (const float*)d_in[5];
    const float* w_gu   = (const float*)d_in[6];
    const float* w_down = (const float*)d_in[7];
    float* out = (float*)d_out;

    float*  qkv_ptr;  cudaGetSymbolAddress((void**)&qkv_ptr,  g_qkv);
    float*  tmp_ptr;  cudaGetSymbolAddress((void**)&tmp_ptr,  g_tmp);
    __half* hidh_ptr; cudaGetSymbolAddress((void**)&hidh_ptr, g_hidh);
    __half* ctxh_ptr; cudaGetSymbolAddress((void**)&ctxh_ptr, g_ctxh);
    __half* wqkvh_ptr;cudaGetSymbolAddress((void**)&wqkvh_ptr,g_wqkvh);
    __half* woh_ptr;  cudaGetSymbolAddress((void**)&woh_ptr,  g_woh);

    const int GEMM_SMEM = (3 * 128 * A32_LD + 3 * 32 * BH_LD) * 2;                     // 56.8 KB
    const int GU_MAIN   = (3 * 128 * A32_LD + 6 * 32 * VH_LD) * 2;                     // 58.4 KB
    const int GU_SMEM   = GU_MAIN > 128 * GC_LD * 4 ? GU_MAIN : 128 * GC_LD * 4;
    const int DOWN_MAIN = (3 * 128 * A32_LD + 3 * 32 * BH_LD) * 2;                     // 56.8 KB
    const int DOWN_SMEM = DOWN_MAIN > 128 * CS_LD * 4 ? DOWN_MAIN : 128 * CS_LD * 4;   // 67.6 KB
    const int ATT_SMEM  = 144384;
    static bool attrs_set = false;
    if (!attrs_set) {
        cudaFuncSetAttribute(gemm_f16_kernel,   cudaFuncAttributeMaxDynamicSharedMemorySize, GEMM_SMEM);
        cudaFuncSetAttribute(moe_gateup_kernel, cudaFuncAttributeMaxDynamicSharedMemorySize, GU_SMEM);
        cudaFuncSetAttribute(moe_down_kernel,   cudaFuncAttributeMaxDynamicSharedMemorySize, DOWN_SMEM);
        cudaFuncSetAttribute(attn_fused_kernel, cudaFuncAttributeMaxDynamicSharedMemorySize, ATT_SMEM);
        attrs_set = true;
    }

    auto cvt = [](const float* in, __half* out, size_t n) {
        cvt_kernel<<<(unsigned)((n / 4 + 255) / 256), 256>>>(in, out, n);
    };

    // 0. f32 -> f16 conversions (small tensors only)
    cvt(hidden, hidh_ptr,  (size_t)T_TOK * H_DIM);
    cvt(w_qkv,  wqkvh_ptr, (size_t)H_DIM * 3 * H_DIM);
    cvt(w_o,    woh_ptr,   (size_t)H_DIM * H_DIM);

    // 1. QKV projection (BK=32, 3-stage)
    gemm_f16_kernel<<<dim3(3072 / 128, 2048 / 128), 256, GEMM_SMEM>>>(hidh_ptr, wqkvh_ptr, qkv_ptr, 2048, 3072, 1024);

    // 2. RoPE -> f16 qkv
    rope_kernel<<<(T_TOK * NHEAD * 32) / 256, 256>>>(cosp, sinp);

    // 3. fused flash attention -> g_ctxh
    attn_fused_kernel<<<dim3(8, 32), 256, ATT_SMEM>>>();

    // 4. O projection
    gemm_f16_kernel<<<dim3(1024 / 128, 2048 / 128), 256, GEMM_SMEM>>>(ctxh_ptr, woh_ptr, tmp_ptr, 2048, 1024, 1024);

    // 5. hs = rmsnorm(x + attn_out)
    addnorm_kernel<<<T_TOK, 256>>>(hidden, tmp_ptr);

    // 6. routing
    zerocnt_kernel<<<1, 32>>>();
    route_kernel<<<T_TOK, 32>>>(w_gate);

    // 7. fused gate_up + silu -> g_acth (f32 weights, 3-stage)
    moe_gateup_kernel<<<dim3(INTER / 64, 2048 / 128, NEXP), 256, GU_SMEM>>>(w_gu);

    // 8. down proj (weighted) -> g_ypair (f32 weights, 3-stage)
    moe_down_kernel<<<dim3(1024 / 128, 2048 / 128, NEXP), 256, DOWN_SMEM>>>(w_down);

    // 9. out = rmsnorm(hs + mixed)
    final_kernel<<<T_TOK, 256>>>(out);
}